// round 2
// baseline (speedup 1.0000x reference)
#include <cuda_runtime.h>
#include <math.h>

// Problem dims (fixed by the dataset)
#define BB 4
#define LL 4096
#define DD 1024
#define NN 64
#define NCH 32            // scan chunks per sequence
#define TCH (LL / NCH)    // 128 steps per chunk

typedef unsigned long long ull;

// ---------------- scratch (device globals: no allocation allowed) ----------------
__device__ float g_Bt[BB * LL * NN];     // softplus gate
__device__ float g_Ct[BB * LL * NN];     // tanh gate
__device__ float g_u[BB * LL * NN];      // x @ Ws + bs
__device__ float g_y[BB * LL * NN];      // scan output
__device__ float g_carry[BB * NCH * NN]; // chunk carries
__device__ float g_ebias[3 * NN];        // effective biases for gate GEMM

// ---------------- helpers ----------------
__device__ __forceinline__ float sp(float v) {           // softplus, stable
    return v > 20.f ? v : log1pf(expf(v));
}

__device__ __forceinline__ ull pk(float lo, float hi) {
    ull r; asm("mov.b64 %0, {%1, %2};" : "=l"(r) : "f"(lo), "f"(hi)); return r;
}
__device__ __forceinline__ void fma2(ull& d, ull a, ull b) {
    asm("fma.rn.f32x2 %0, %1, %2, %0;" : "+l"(d) : "l"(a), "l"(b));
}
__device__ __forceinline__ float2 upk(ull v) {
    float2 f; asm("mov.b64 {%0, %1}, %2;" : "=f"(f.x), "=f"(f.y) : "l"(v)); return f;
}

__device__ __forceinline__ float4 f4fma(float4 acc, float4 a, float4 b) {
    acc.x = fmaf(a.x, b.x, acc.x);
    acc.y = fmaf(a.y, b.y, acc.y);
    acc.z = fmaf(a.z, b.z, acc.z);
    acc.w = fmaf(a.w, b.w, acc.w);
    return acc;
}

// ---------------- kernel 0: effective bias for the gate GEMM ----------------
// ebias[0:64]   = bp[0:64]   + conv_b @ Wp[:, 0:64]
// ebias[64:128] = bp[64:128] + conv_b @ Wp[:, 64:128]
// ebias[128:192]= bs
__global__ void __launch_bounds__(192) ebias_kernel(
    const float* __restrict__ cb, const float* __restrict__ Wp,
    const float* __restrict__ bp, const float* __restrict__ bs,
    float* __restrict__ ebias)
{
    const int n = threadIdx.x;
    if (n < 2 * NN) {
        float s = bp[n];
#pragma unroll 8
        for (int d = 0; d < DD; ++d) s = fmaf(cb[d], Wp[(size_t)d * 2 * NN + n], s);
        ebias[n] = s;
    } else {
        ebias[n] = bs[n - 2 * NN];
    }
}

// ---------------- kernel 1: fused conv + gate GEMMs ----------------
// blockIdx.y selects output:
//   0: Bt = softplus(conv(x) @ Wp[:, :64]  + ebias[0:64])
//   1: Ct = tanh   (conv(x) @ Wp[:, 64:]  + ebias[64:128])
//   2: u  =         x       @ Ws          + ebias[128:192]
// conv(x)[l,d] = w[0,d]x[l-3,d] + w[1,d]x[l-2,d] + w[2,d]x[l-1,d] + w[3,d]x[l,d]
// (conv_b folded into ebias). 64x64 tile, BK=16, 128 threads, 8x4 microtile,
// packed f32x2 FFMA.
__global__ void __launch_bounds__(128) gate_gemm(
    const float* __restrict__ x, const float* __restrict__ cw,
    const float* __restrict__ Wp, const float* __restrict__ Ws,
    const float* __restrict__ ebias,
    float* __restrict__ Bt, float* __restrict__ Ct, float* __restrict__ u)
{
    __shared__ __align__(16) float As[16][64];
    __shared__ __align__(16) float Bs[16][64];

    const int tid = threadIdx.x;
    const int m0  = blockIdx.x * 64;
    const int j   = blockIdx.y;               // 0,1,2

    const float* Bm; int ldb; float* C;
    if (j == 0)      { Bm = Wp;      ldb = 2 * NN; C = Bt; }
    else if (j == 1) { Bm = Wp + NN; ldb = 2 * NN; C = Ct; }
    else             { Bm = Ws;      ldb = NN;     C = u;  }

    // global-load mapping
    const int ar = tid >> 2;             // 0..31: A rows ar, ar+32
    const int ac = (tid & 3) * 4;        // k-offset within tile
    const int br = tid >> 4;             // 0..7: B k-rows br, br+8
    const int bc = (tid & 15) * 4;       // col offset

    // compute mapping
    const int tx = tid & 15, ty = tid >> 4;
    const int r0 = ty * 8, c0 = tx * 4;

    const int rg0 = m0 + ar;             // global A rows for this thread
    const int rg1 = m0 + ar + 32;
    const int l0 = rg0 & (LL - 1);       // position within sequence
    const int l1 = rg1 & (LL - 1);
    const float* xr0 = x + (size_t)rg0 * DD;
    const float* xr1 = x + (size_t)rg1 * DD;

    ull acc[8][2];
#pragma unroll
    for (int i = 0; i < 8; ++i) { acc[i][0] = 0ull; acc[i][1] = 0ull; }

    const float4 z4 = make_float4(0.f, 0.f, 0.f, 0.f);

    for (int kt = 0; kt < DD / 16; ++kt) {
        const int col = kt * 16 + ac;

        // ---- stage A tile (with on-the-fly conv for j<2) ----
        float4 a0, a1;
        if (j < 2) {
            float4 w0 = *(const float4*)&cw[0 * DD + col];
            float4 w1 = *(const float4*)&cw[1 * DD + col];
            float4 w2 = *(const float4*)&cw[2 * DD + col];
            float4 w3 = *(const float4*)&cw[3 * DD + col];
            {
                float4 c0v = *(const float4*)(xr0 + col);
                float4 c1v = (l0 >= 1) ? *(const float4*)(xr0 + col - DD)     : z4;
                float4 c2v = (l0 >= 2) ? *(const float4*)(xr0 + col - 2 * DD) : z4;
                float4 c3v = (l0 >= 3) ? *(const float4*)(xr0 + col - 3 * DD) : z4;
                float4 o = make_float4(0.f, 0.f, 0.f, 0.f);
                o = f4fma(o, w0, c3v); o = f4fma(o, w1, c2v);
                o = f4fma(o, w2, c1v); o = f4fma(o, w3, c0v);
                a0 = o;
            }
            {
                float4 c0v = *(const float4*)(xr1 + col);
                float4 c1v = (l1 >= 1) ? *(const float4*)(xr1 + col - DD)     : z4;
                float4 c2v = (l1 >= 2) ? *(const float4*)(xr1 + col - 2 * DD) : z4;
                float4 c3v = (l1 >= 3) ? *(const float4*)(xr1 + col - 3 * DD) : z4;
                float4 o = make_float4(0.f, 0.f, 0.f, 0.f);
                o = f4fma(o, w0, c3v); o = f4fma(o, w1, c2v);
                o = f4fma(o, w2, c1v); o = f4fma(o, w3, c0v);
                a1 = o;
            }
        } else {
            a0 = *(const float4*)(xr0 + col);
            a1 = *(const float4*)(xr1 + col);
        }
        // A transposed in smem: As[k][m]
        As[ac + 0][ar] = a0.x; As[ac + 1][ar] = a0.y;
        As[ac + 2][ar] = a0.z; As[ac + 3][ar] = a0.w;
        As[ac + 0][ar + 32] = a1.x; As[ac + 1][ar + 32] = a1.y;
        As[ac + 2][ar + 32] = a1.z; As[ac + 3][ar + 32] = a1.w;

        // ---- stage B tile ----
        *(float4*)&Bs[br][bc]     = *(const float4*)&Bm[(size_t)(kt * 16 + br) * ldb + bc];
        *(float4*)&Bs[br + 8][bc] = *(const float4*)&Bm[(size_t)(kt * 16 + br + 8) * ldb + bc];
        __syncthreads();

#pragma unroll
        for (int k = 0; k < 16; ++k) {
            float4 va0 = *(const float4*)&As[k][r0];
            float4 va1 = *(const float4*)&As[k][r0 + 4];
            ull vb01 = *(const ull*)&Bs[k][c0];
            ull vb23 = *(const ull*)&Bs[k][c0 + 2];
            ull d;
            d = pk(va0.x, va0.x); fma2(acc[0][0], d, vb01); fma2(acc[0][1], d, vb23);
            d = pk(va0.y, va0.y); fma2(acc[1][0], d, vb01); fma2(acc[1][1], d, vb23);
            d = pk(va0.z, va0.z); fma2(acc[2][0], d, vb01); fma2(acc[2][1], d, vb23);
            d = pk(va0.w, va0.w); fma2(acc[3][0], d, vb01); fma2(acc[3][1], d, vb23);
            d = pk(va1.x, va1.x); fma2(acc[4][0], d, vb01); fma2(acc[4][1], d, vb23);
            d = pk(va1.y, va1.y); fma2(acc[5][0], d, vb01); fma2(acc[5][1], d, vb23);
            d = pk(va1.z, va1.z); fma2(acc[6][0], d, vb01); fma2(acc[6][1], d, vb23);
            d = pk(va1.w, va1.w); fma2(acc[7][0], d, vb01); fma2(acc[7][1], d, vb23);
        }
        __syncthreads();
    }

    // epilogue: bias + activation
    float4 bb = *(const float4*)&ebias[j * NN + c0];
#pragma unroll
    for (int i = 0; i < 8; ++i) {
        float2 v0 = upk(acc[i][0]);
        float2 v1 = upk(acc[i][1]);
        float4 o = make_float4(v0.x + bb.x, v0.y + bb.y, v1.x + bb.z, v1.y + bb.w);
        if (j == 0) {
            o.x = sp(o.x); o.y = sp(o.y); o.z = sp(o.z); o.w = sp(o.w);
        } else if (j == 1) {
            o.x = tanhf(o.x); o.y = tanhf(o.y); o.z = tanhf(o.z); o.w = tanhf(o.w);
        }
        int row = m0 + r0 + i;
        *(float4*)&C[(size_t)row * NN + c0] = o;
    }
}

// ---------------- kernel 2: fp32 GEMM (output projection) ----------------
// C[m,n] = sum_k A[m,k]*Bm[k,n] + bias[n]. 64x64 tile, BK=16, prefetched.
__global__ void __launch_bounds__(128) gemm64(
    const float* __restrict__ A, int lda,
    const float* __restrict__ Bm, int ldb,
    const float* __restrict__ bias,
    float* __restrict__ C, int ldc,
    int Ktot)
{
    __shared__ __align__(16) float As[16][64];
    __shared__ __align__(16) float Bs[16][64];

    const int tid = threadIdx.x;
    const int m0 = blockIdx.x * 64;
    const int n0 = blockIdx.y * 64;

    const int ar = tid >> 2;
    const int ac = (tid & 3) * 4;
    const int br = tid >> 4;
    const int bc = (tid & 15) * 4;

    const int tx = tid & 15, ty = tid >> 4;
    const int r0 = ty * 8, c0 = tx * 4;

    const int nt = Ktot / 16;
    const float* Ag0 = A + (size_t)(m0 + ar) * lda + ac;
    const float* Ag1 = A + (size_t)(m0 + ar + 32) * lda + ac;
    const float* Bg0 = Bm + (size_t)br * ldb + n0 + bc;
    const float* Bg1 = Bm + (size_t)(br + 8) * ldb + n0 + bc;

    float4 a0 = *(const float4*)Ag0;
    float4 a1 = *(const float4*)Ag1;
    float4 b0 = *(const float4*)Bg0;
    float4 b1 = *(const float4*)Bg1;

    ull acc[8][2];
#pragma unroll
    for (int i = 0; i < 8; ++i) { acc[i][0] = 0ull; acc[i][1] = 0ull; }

    for (int kt = 0; kt < nt; ++kt) {
        As[ac + 0][ar] = a0.x; As[ac + 1][ar] = a0.y;
        As[ac + 2][ar] = a0.z; As[ac + 3][ar] = a0.w;
        As[ac + 0][ar + 32] = a1.x; As[ac + 1][ar + 32] = a1.y;
        As[ac + 2][ar + 32] = a1.z; As[ac + 3][ar + 32] = a1.w;
        *(float4*)&Bs[br][bc]     = b0;
        *(float4*)&Bs[br + 8][bc] = b1;
        __syncthreads();

        if (kt + 1 < nt) {
            a0 = *(const float4*)(Ag0 + (kt + 1) * 16);
            a1 = *(const float4*)(Ag1 + (kt + 1) * 16);
            b0 = *(const float4*)(Bg0 + (size_t)(kt + 1) * 16 * ldb);
            b1 = *(const float4*)(Bg1 + (size_t)(kt + 1) * 16 * ldb);
        }

#pragma unroll
        for (int k = 0; k < 16; ++k) {
            float4 va0 = *(const float4*)&As[k][r0];
            float4 va1 = *(const float4*)&As[k][r0 + 4];
            ull vb01 = *(const ull*)&Bs[k][c0];
            ull vb23 = *(const ull*)&Bs[k][c0 + 2];
            ull d;
            d = pk(va0.x, va0.x); fma2(acc[0][0], d, vb01); fma2(acc[0][1], d, vb23);
            d = pk(va0.y, va0.y); fma2(acc[1][0], d, vb01); fma2(acc[1][1], d, vb23);
            d = pk(va0.z, va0.z); fma2(acc[2][0], d, vb01); fma2(acc[2][1], d, vb23);
            d = pk(va0.w, va0.w); fma2(acc[3][0], d, vb01); fma2(acc[3][1], d, vb23);
            d = pk(va1.x, va1.x); fma2(acc[4][0], d, vb01); fma2(acc[4][1], d, vb23);
            d = pk(va1.y, va1.y); fma2(acc[5][0], d, vb01); fma2(acc[5][1], d, vb23);
            d = pk(va1.z, va1.z); fma2(acc[6][0], d, vb01); fma2(acc[6][1], d, vb23);
            d = pk(va1.w, va1.w); fma2(acc[7][0], d, vb01); fma2(acc[7][1], d, vb23);
        }
        __syncthreads();
    }

    float4 bb = *(const float4*)&bias[n0 + c0];
#pragma unroll
    for (int i = 0; i < 8; ++i) {
        float2 v0 = upk(acc[i][0]);
        float2 v1 = upk(acc[i][1]);
        float4 o = make_float4(v0.x + bb.x, v0.y + bb.y, v1.x + bb.z, v1.y + bb.w);
        int row = m0 + r0 + i;
        *(float4*)&C[(size_t)row * ldc + n0 + c0] = o;
    }
}

// ---------------- scan kernels (chunk-parallel linear recurrence) ----------------
__global__ void __launch_bounds__(64) scan_partial(
    const float* __restrict__ A_log, const float* __restrict__ dt_log,
    const float* __restrict__ u, const float* __restrict__ Bt,
    float* __restrict__ carry)
{
    const int n = threadIdx.x, ch = blockIdx.x, b = blockIdx.y;
    const float dt = sp(dt_log[n]);
    const float decay = 1.f - dt * sp(A_log[n]);
    size_t base = ((size_t)b * LL + (size_t)ch * TCH) * NN + n;
    float s = 0.f;
#pragma unroll 4
    for (int t = 0; t < TCH; ++t) {
        float uu = u[base + (size_t)t * NN];
        float bt = Bt[base + (size_t)t * NN];
        s = fmaf(decay, s, (dt * bt) * uu);
    }
    carry[((size_t)b * NCH + ch) * NN + n] = s;
}

__global__ void __launch_bounds__(256) scan_carry(
    const float* __restrict__ A_log, const float* __restrict__ dt_log,
    float* __restrict__ carry)
{
    const int tid = threadIdx.x;
    const int b = tid >> 6, n = tid & 63;
    const float dt = sp(dt_log[n]);
    const float decay = 1.f - dt * sp(A_log[n]);
    float dp = decay;
#pragma unroll
    for (int i = 0; i < 7; ++i) dp *= dp;          // decay^128 (TCH = 2^7)
    float c = 0.f;
    for (int ch = 0; ch < NCH; ++ch) {
        size_t idx = ((size_t)b * NCH + ch) * NN + n;
        float e = carry[idx];
        carry[idx] = c;                             // carry_in for this chunk
        c = fmaf(dp, c, e);
    }
}

__global__ void __launch_bounds__(64) scan_final(
    const float* __restrict__ A_log, const float* __restrict__ dt_log,
    const float* __restrict__ u, const float* __restrict__ Bt,
    const float* __restrict__ Ct, const float* __restrict__ carry,
    float* __restrict__ y)
{
    const int n = threadIdx.x, ch = blockIdx.x, b = blockIdx.y;
    const float dt = sp(dt_log[n]);
    const float decay = 1.f - dt * sp(A_log[n]);
    size_t base = ((size_t)b * LL + (size_t)ch * TCH) * NN + n;
    float s = carry[((size_t)b * NCH + ch) * NN + n];
#pragma unroll 4
    for (int t = 0; t < TCH; ++t) {
        float uu = u[base + (size_t)t * NN];
        float bt = Bt[base + (size_t)t * NN];
        float ct = Ct[base + (size_t)t * NN];
        s = fmaf(decay, s, (dt * bt) * uu);
        y[base + (size_t)t * NN] = ct * s;
    }
}

// ---------------- launch ----------------
extern "C" void kernel_launch(void* const* d_in, const int* in_sizes, int n_in,
                              void* d_out, int out_size)
{
    const float* x      = (const float*)d_in[0];
    const float* conv_w = (const float*)d_in[1];
    const float* conv_b = (const float*)d_in[2];
    const float* Wp     = (const float*)d_in[3];
    const float* bp     = (const float*)d_in[4];
    const float* Ws     = (const float*)d_in[5];
    const float* bs     = (const float*)d_in[6];
    const float* A_log  = (const float*)d_in[7];
    const float* dt_log = (const float*)d_in[8];
    const float* Wo     = (const float*)d_in[9];
    const float* bo     = (const float*)d_in[10];
    float* out = (float*)d_out;

    float *bt_p, *ct_p, *u_p, *y_p, *carry_p, *ebias_p;
    cudaGetSymbolAddress((void**)&bt_p,    g_Bt);
    cudaGetSymbolAddress((void**)&ct_p,    g_Ct);
    cudaGetSymbolAddress((void**)&u_p,     g_u);
    cudaGetSymbolAddress((void**)&y_p,     g_y);
    cudaGetSymbolAddress((void**)&carry_p, g_carry);
    cudaGetSymbolAddress((void**)&ebias_p, g_ebias);

    const int M = BB * LL;   // 16384

    // 0) effective biases
    ebias_kernel<<<1, 192>>>(conv_b, Wp, bp, bs, ebias_p);

    // 1) fused conv + gate GEMMs (Bt, Ct, u)
    gate_gemm<<<dim3(M / 64, 3), 128>>>(x, conv_w, Wp, Ws, ebias_p, bt_p, ct_p, u_p);

    // 2) chunk-parallel scan -> y
    scan_partial<<<dim3(NCH, BB), 64>>>(A_log, dt_log, u_p, bt_p, carry_p);
    scan_carry<<<1, 256>>>(A_log, dt_log, carry_p);
    scan_final<<<dim3(NCH, BB), 64>>>(A_log, dt_log, u_p, bt_p, ct_p, carry_p, y_p);

    // 3) out = y @ Wo + bo
    gemm64<<<dim3(M / 64, DD / 64), 128>>>(y_p, NN, Wo, DD, bo, out, DD, NN);
}

// round 3
// speedup vs baseline: 1.0015x; 1.0015x over previous
#include <cuda_runtime.h>
#include <math.h>

// Problem dims (fixed by the dataset)
#define BB 4
#define LL 4096
#define DD 1024
#define NN 64
#define NCH 32            // scan chunks per sequence
#define TCH (LL / NCH)    // 128 steps per chunk

typedef unsigned long long ull;

// ---------------- scratch (device globals: no allocation allowed) ----------------
__device__ float g_Bt[BB * LL * NN];     // softplus gate
__device__ float g_Ct[BB * LL * NN];     // tanh gate
__device__ float g_u[BB * LL * NN];      // x @ Ws + bs
__device__ float g_y[BB * LL * NN];      // scan output
__device__ float g_carry[BB * NCH * NN]; // chunk carries
__device__ float g_ebias[3 * NN];        // effective biases for gate GEMM

// ---------------- helpers ----------------
__device__ __forceinline__ float sp(float v) {           // softplus, stable
    return v > 20.f ? v : log1pf(expf(v));
}

__device__ __forceinline__ ull pk(float lo, float hi) {
    ull r; asm("mov.b64 %0, {%1, %2};" : "=l"(r) : "f"(lo), "f"(hi)); return r;
}
__device__ __forceinline__ void fma2(ull& d, ull a, ull b) {
    asm("fma.rn.f32x2 %0, %1, %2, %0;" : "+l"(d) : "l"(a), "l"(b));
}
__device__ __forceinline__ float2 upk(ull v) {
    float2 f; asm("mov.b64 {%0, %1}, %2;" : "=f"(f.x), "=f"(f.y) : "l"(v)); return f;
}

__device__ __forceinline__ float4 f4fma(float4 acc, float4 a, float4 b) {
    acc.x = fmaf(a.x, b.x, acc.x);
    acc.y = fmaf(a.y, b.y, acc.y);
    acc.z = fmaf(a.z, b.z, acc.z);
    acc.w = fmaf(a.w, b.w, acc.w);
    return acc;
}

// ---------------- kernel 0: effective bias for the gate GEMM ----------------
// ebias[0:64]   = bp[0:64]   + conv_b @ Wp[:, 0:64]
// ebias[64:128] = bp[64:128] + conv_b @ Wp[:, 64:128]
// ebias[128:192]= bs
__global__ void __launch_bounds__(192) ebias_kernel(
    const float* __restrict__ cb, const float* __restrict__ Wp,
    const float* __restrict__ bp, const float* __restrict__ bs,
    float* __restrict__ ebias)
{
    const int n = threadIdx.x;
    if (n < 2 * NN) {
        float s = bp[n];
#pragma unroll 8
        for (int d = 0; d < DD; ++d) s = fmaf(cb[d], Wp[(size_t)d * 2 * NN + n], s);
        ebias[n] = s;
    } else {
        ebias[n] = bs[n - 2 * NN];
    }
}

// ---------------- kernel 1: fused conv + gate GEMMs ----------------
// blockIdx.y selects output:
//   0: Bt = softplus(conv(x) @ Wp[:, :64]  + ebias[0:64])
//   1: Ct = tanh   (conv(x) @ Wp[:, 64:]  + ebias[64:128])
//   2: u  =         x       @ Ws          + ebias[128:192]
// conv(x)[l,d] = w[0,d]x[l-3,d] + w[1,d]x[l-2,d] + w[2,d]x[l-1,d] + w[3,d]x[l,d]
// (conv_b folded into ebias). 64x64 tile, BK=16, 128 threads, 8x4 microtile,
// packed f32x2 FFMA.
__global__ void __launch_bounds__(128) gate_gemm(
    const float* __restrict__ x, const float* __restrict__ cw,
    const float* __restrict__ Wp, const float* __restrict__ Ws,
    const float* __restrict__ ebias,
    float* __restrict__ Bt, float* __restrict__ Ct, float* __restrict__ u)
{
    __shared__ __align__(16) float As[16][64];
    __shared__ __align__(16) float Bs[16][64];

    const int tid = threadIdx.x;
    const int m0  = blockIdx.x * 64;
    const int j   = blockIdx.y;               // 0,1,2

    const float* Bm; int ldb; float* C;
    if (j == 0)      { Bm = Wp;      ldb = 2 * NN; C = Bt; }
    else if (j == 1) { Bm = Wp + NN; ldb = 2 * NN; C = Ct; }
    else             { Bm = Ws;      ldb = NN;     C = u;  }

    // global-load mapping
    const int ar = tid >> 2;             // 0..31: A rows ar, ar+32
    const int ac = (tid & 3) * 4;        // k-offset within tile
    const int br = tid >> 4;             // 0..7: B k-rows br, br+8
    const int bc = (tid & 15) * 4;       // col offset

    // compute mapping
    const int tx = tid & 15, ty = tid >> 4;
    const int r0 = ty * 8, c0 = tx * 4;

    const int rg0 = m0 + ar;             // global A rows for this thread
    const int rg1 = m0 + ar + 32;
    const int l0 = rg0 & (LL - 1);       // position within sequence
    const int l1 = rg1 & (LL - 1);
    const float* xr0 = x + (size_t)rg0 * DD;
    const float* xr1 = x + (size_t)rg1 * DD;

    ull acc[8][2];
#pragma unroll
    for (int i = 0; i < 8; ++i) { acc[i][0] = 0ull; acc[i][1] = 0ull; }

    const float4 z4 = make_float4(0.f, 0.f, 0.f, 0.f);

    for (int kt = 0; kt < DD / 16; ++kt) {
        const int col = kt * 16 + ac;

        // ---- stage A tile (with on-the-fly conv for j<2) ----
        float4 a0, a1;
        if (j < 2) {
            float4 w0 = *(const float4*)&cw[0 * DD + col];
            float4 w1 = *(const float4*)&cw[1 * DD + col];
            float4 w2 = *(const float4*)&cw[2 * DD + col];
            float4 w3 = *(const float4*)&cw[3 * DD + col];
            {
                float4 c0v = *(const float4*)(xr0 + col);
                float4 c1v = (l0 >= 1) ? *(const float4*)(xr0 + col - DD)     : z4;
                float4 c2v = (l0 >= 2) ? *(const float4*)(xr0 + col - 2 * DD) : z4;
                float4 c3v = (l0 >= 3) ? *(const float4*)(xr0 + col - 3 * DD) : z4;
                float4 o = make_float4(0.f, 0.f, 0.f, 0.f);
                o = f4fma(o, w0, c3v); o = f4fma(o, w1, c2v);
                o = f4fma(o, w2, c1v); o = f4fma(o, w3, c0v);
                a0 = o;
            }
            {
                float4 c0v = *(const float4*)(xr1 + col);
                float4 c1v = (l1 >= 1) ? *(const float4*)(xr1 + col - DD)     : z4;
                float4 c2v = (l1 >= 2) ? *(const float4*)(xr1 + col - 2 * DD) : z4;
                float4 c3v = (l1 >= 3) ? *(const float4*)(xr1 + col - 3 * DD) : z4;
                float4 o = make_float4(0.f, 0.f, 0.f, 0.f);
                o = f4fma(o, w0, c3v); o = f4fma(o, w1, c2v);
                o = f4fma(o, w2, c1v); o = f4fma(o, w3, c0v);
                a1 = o;
            }
        } else {
            a0 = *(const float4*)(xr0 + col);
            a1 = *(const float4*)(xr1 + col);
        }
        // A transposed in smem: As[k][m]
        As[ac + 0][ar] = a0.x; As[ac + 1][ar] = a0.y;
        As[ac + 2][ar] = a0.z; As[ac + 3][ar] = a0.w;
        As[ac + 0][ar + 32] = a1.x; As[ac + 1][ar + 32] = a1.y;
        As[ac + 2][ar + 32] = a1.z; As[ac + 3][ar + 32] = a1.w;

        // ---- stage B tile ----
        *(float4*)&Bs[br][bc]     = *(const float4*)&Bm[(size_t)(kt * 16 + br) * ldb + bc];
        *(float4*)&Bs[br + 8][bc] = *(const float4*)&Bm[(size_t)(kt * 16 + br + 8) * ldb + bc];
        __syncthreads();

#pragma unroll
        for (int k = 0; k < 16; ++k) {
            float4 va0 = *(const float4*)&As[k][r0];
            float4 va1 = *(const float4*)&As[k][r0 + 4];
            ull vb01 = *(const ull*)&Bs[k][c0];
            ull vb23 = *(const ull*)&Bs[k][c0 + 2];
            ull d;
            d = pk(va0.x, va0.x); fma2(acc[0][0], d, vb01); fma2(acc[0][1], d, vb23);
            d = pk(va0.y, va0.y); fma2(acc[1][0], d, vb01); fma2(acc[1][1], d, vb23);
            d = pk(va0.z, va0.z); fma2(acc[2][0], d, vb01); fma2(acc[2][1], d, vb23);
            d = pk(va0.w, va0.w); fma2(acc[3][0], d, vb01); fma2(acc[3][1], d, vb23);
            d = pk(va1.x, va1.x); fma2(acc[4][0], d, vb01); fma2(acc[4][1], d, vb23);
            d = pk(va1.y, va1.y); fma2(acc[5][0], d, vb01); fma2(acc[5][1], d, vb23);
            d = pk(va1.z, va1.z); fma2(acc[6][0], d, vb01); fma2(acc[6][1], d, vb23);
            d = pk(va1.w, va1.w); fma2(acc[7][0], d, vb01); fma2(acc[7][1], d, vb23);
        }
        __syncthreads();
    }

    // epilogue: bias + activation
    float4 bb = *(const float4*)&ebias[j * NN + c0];
#pragma unroll
    for (int i = 0; i < 8; ++i) {
        float2 v0 = upk(acc[i][0]);
        float2 v1 = upk(acc[i][1]);
        float4 o = make_float4(v0.x + bb.x, v0.y + bb.y, v1.x + bb.z, v1.y + bb.w);
        if (j == 0) {
            o.x = sp(o.x); o.y = sp(o.y); o.z = sp(o.z); o.w = sp(o.w);
        } else if (j == 1) {
            o.x = tanhf(o.x); o.y = tanhf(o.y); o.z = tanhf(o.z); o.w = tanhf(o.w);
        }
        int row = m0 + r0 + i;
        *(float4*)&C[(size_t)row * NN + c0] = o;
    }
}

// ---------------- kernel 2: fp32 GEMM (output projection) ----------------
// C[m,n] = sum_k A[m,k]*Bm[k,n] + bias[n]. 64x64 tile, BK=16, prefetched.
__global__ void __launch_bounds__(128) gemm64(
    const float* __restrict__ A, int lda,
    const float* __restrict__ Bm, int ldb,
    const float* __restrict__ bias,
    float* __restrict__ C, int ldc,
    int Ktot)
{
    __shared__ __align__(16) float As[16][64];
    __shared__ __align__(16) float Bs[16][64];

    const int tid = threadIdx.x;
    const int m0 = blockIdx.x * 64;
    const int n0 = blockIdx.y * 64;

    const int ar = tid >> 2;
    const int ac = (tid & 3) * 4;
    const int br = tid >> 4;
    const int bc = (tid & 15) * 4;

    const int tx = tid & 15, ty = tid >> 4;
    const int r0 = ty * 8, c0 = tx * 4;

    const int nt = Ktot / 16;
    const float* Ag0 = A + (size_t)(m0 + ar) * lda + ac;
    const float* Ag1 = A + (size_t)(m0 + ar + 32) * lda + ac;
    const float* Bg0 = Bm + (size_t)br * ldb + n0 + bc;
    const float* Bg1 = Bm + (size_t)(br + 8) * ldb + n0 + bc;

    float4 a0 = *(const float4*)Ag0;
    float4 a1 = *(const float4*)Ag1;
    float4 b0 = *(const float4*)Bg0;
    float4 b1 = *(const float4*)Bg1;

    ull acc[8][2];
#pragma unroll
    for (int i = 0; i < 8; ++i) { acc[i][0] = 0ull; acc[i][1] = 0ull; }

    for (int kt = 0; kt < nt; ++kt) {
        As[ac + 0][ar] = a0.x; As[ac + 1][ar] = a0.y;
        As[ac + 2][ar] = a0.z; As[ac + 3][ar] = a0.w;
        As[ac + 0][ar + 32] = a1.x; As[ac + 1][ar + 32] = a1.y;
        As[ac + 2][ar + 32] = a1.z; As[ac + 3][ar + 32] = a1.w;
        *(float4*)&Bs[br][bc]     = b0;
        *(float4*)&Bs[br + 8][bc] = b1;
        __syncthreads();

        if (kt + 1 < nt) {
            a0 = *(const float4*)(Ag0 + (kt + 1) * 16);
            a1 = *(const float4*)(Ag1 + (kt + 1) * 16);
            b0 = *(const float4*)(Bg0 + (size_t)(kt + 1) * 16 * ldb);
            b1 = *(const float4*)(Bg1 + (size_t)(kt + 1) * 16 * ldb);
        }

#pragma unroll
        for (int k = 0; k < 16; ++k) {
            float4 va0 = *(const float4*)&As[k][r0];
            float4 va1 = *(const float4*)&As[k][r0 + 4];
            ull vb01 = *(const ull*)&Bs[k][c0];
            ull vb23 = *(const ull*)&Bs[k][c0 + 2];
            ull d;
            d = pk(va0.x, va0.x); fma2(acc[0][0], d, vb01); fma2(acc[0][1], d, vb23);
            d = pk(va0.y, va0.y); fma2(acc[1][0], d, vb01); fma2(acc[1][1], d, vb23);
            d = pk(va0.z, va0.z); fma2(acc[2][0], d, vb01); fma2(acc[2][1], d, vb23);
            d = pk(va0.w, va0.w); fma2(acc[3][0], d, vb01); fma2(acc[3][1], d, vb23);
            d = pk(va1.x, va1.x); fma2(acc[4][0], d, vb01); fma2(acc[4][1], d, vb23);
            d = pk(va1.y, va1.y); fma2(acc[5][0], d, vb01); fma2(acc[5][1], d, vb23);
            d = pk(va1.z, va1.z); fma2(acc[6][0], d, vb01); fma2(acc[6][1], d, vb23);
            d = pk(va1.w, va1.w); fma2(acc[7][0], d, vb01); fma2(acc[7][1], d, vb23);
        }
        __syncthreads();
    }

    float4 bb = *(const float4*)&bias[n0 + c0];
#pragma unroll
    for (int i = 0; i < 8; ++i) {
        float2 v0 = upk(acc[i][0]);
        float2 v1 = upk(acc[i][1]);
        float4 o = make_float4(v0.x + bb.x, v0.y + bb.y, v1.x + bb.z, v1.y + bb.w);
        int row = m0 + r0 + i;
        *(float4*)&C[(size_t)row * ldc + n0 + c0] = o;
    }
}

// ---------------- scan kernels (chunk-parallel linear recurrence) ----------------
__global__ void __launch_bounds__(64) scan_partial(
    const float* __restrict__ A_log, const float* __restrict__ dt_log,
    const float* __restrict__ u, const float* __restrict__ Bt,
    float* __restrict__ carry)
{
    const int n = threadIdx.x, ch = blockIdx.x, b = blockIdx.y;
    const float dt = sp(dt_log[n]);
    const float decay = 1.f - dt * sp(A_log[n]);
    size_t base = ((size_t)b * LL + (size_t)ch * TCH) * NN + n;
    float s = 0.f;
#pragma unroll 4
    for (int t = 0; t < TCH; ++t) {
        float uu = u[base + (size_t)t * NN];
        float bt = Bt[base + (size_t)t * NN];
        s = fmaf(decay, s, (dt * bt) * uu);
    }
    carry[((size_t)b * NCH + ch) * NN + n] = s;
}

__global__ void __launch_bounds__(256) scan_carry(
    const float* __restrict__ A_log, const float* __restrict__ dt_log,
    float* __restrict__ carry)
{
    const int tid = threadIdx.x;
    const int b = tid >> 6, n = tid & 63;
    const float dt = sp(dt_log[n]);
    const float decay = 1.f - dt * sp(A_log[n]);
    float dp = decay;
#pragma unroll
    for (int i = 0; i < 7; ++i) dp *= dp;          // decay^128 (TCH = 2^7)
    float c = 0.f;
    for (int ch = 0; ch < NCH; ++ch) {
        size_t idx = ((size_t)b * NCH + ch) * NN + n;
        float e = carry[idx];
        carry[idx] = c;                             // carry_in for this chunk
        c = fmaf(dp, c, e);
    }
}

__global__ void __launch_bounds__(64) scan_final(
    const float* __restrict__ A_log, const float* __restrict__ dt_log,
    const float* __restrict__ u, const float* __restrict__ Bt,
    const float* __restrict__ Ct, const float* __restrict__ carry,
    float* __restrict__ y)
{
    const int n = threadIdx.x, ch = blockIdx.x, b = blockIdx.y;
    const float dt = sp(dt_log[n]);
    const float decay = 1.f - dt * sp(A_log[n]);
    size_t base = ((size_t)b * LL + (size_t)ch * TCH) * NN + n;
    float s = carry[((size_t)b * NCH + ch) * NN + n];
#pragma unroll 4
    for (int t = 0; t < TCH; ++t) {
        float uu = u[base + (size_t)t * NN];
        float bt = Bt[base + (size_t)t * NN];
        float ct = Ct[base + (size_t)t * NN];
        s = fmaf(decay, s, (dt * bt) * uu);
        y[base + (size_t)t * NN] = ct * s;
    }
}

// ---------------- launch ----------------
extern "C" void kernel_launch(void* const* d_in, const int* in_sizes, int n_in,
                              void* d_out, int out_size)
{
    const float* x      = (const float*)d_in[0];
    const float* conv_w = (const float*)d_in[1];
    const float* conv_b = (const float*)d_in[2];
    const float* Wp     = (const float*)d_in[3];
    const float* bp     = (const float*)d_in[4];
    const float* Ws     = (const float*)d_in[5];
    const float* bs     = (const float*)d_in[6];
    const float* A_log  = (const float*)d_in[7];
    const float* dt_log = (const float*)d_in[8];
    const float* Wo     = (const float*)d_in[9];
    const float* bo     = (const float*)d_in[10];
    float* out = (float*)d_out;

    float *bt_p, *ct_p, *u_p, *y_p, *carry_p, *ebias_p;
    cudaGetSymbolAddress((void**)&bt_p,    g_Bt);
    cudaGetSymbolAddress((void**)&ct_p,    g_Ct);
    cudaGetSymbolAddress((void**)&u_p,     g_u);
    cudaGetSymbolAddress((void**)&y_p,     g_y);
    cudaGetSymbolAddress((void**)&carry_p, g_carry);
    cudaGetSymbolAddress((void**)&ebias_p, g_ebias);

    const int M = BB * LL;   // 16384

    // 0) effective biases
    ebias_kernel<<<1, 192>>>(conv_b, Wp, bp, bs, ebias_p);

    // 1) fused conv + gate GEMMs (Bt, Ct, u)
    gate_gemm<<<dim3(M / 64, 3), 128>>>(x, conv_w, Wp, Ws, ebias_p, bt_p, ct_p, u_p);

    // 2) chunk-parallel scan -> y
    scan_partial<<<dim3(NCH, BB), 64>>>(A_log, dt_log, u_p, bt_p, carry_p);
    scan_carry<<<1, 256>>>(A_log, dt_log, carry_p);
    scan_final<<<dim3(NCH, BB), 64>>>(A_log, dt_log, u_p, bt_p, ct_p, carry_p, y_p);

    // 3) out = y @ Wo + bo
    gemm64<<<dim3(M / 64, DD / 64), 128>>>(y_p, NN, Wo, DD, bo, out, DD, NN);
}

// round 4
// speedup vs baseline: 1.0044x; 1.0029x over previous
#include <cuda_runtime.h>
#include <math.h>

// Problem dims (fixed by the dataset)
#define BB 4
#define LL 4096
#define DD 1024
#define NN 64
#define NCH 32            // scan chunks per sequence
#define TCH (LL / NCH)    // 128 steps per chunk

typedef unsigned long long ull;

// ---------------- scratch (device globals: no allocation allowed) ----------------
__device__ float g_Bt[BB * LL * NN];     // softplus gate
__device__ float g_Ct[BB * LL * NN];     // tanh gate
__device__ float g_u[BB * LL * NN];      // x @ Ws + bs
__device__ float g_y[BB * LL * NN];      // scan output
__device__ float g_carry[BB * NCH * NN]; // chunk carries
__device__ float g_ebias[3 * NN];        // effective biases for gate GEMM

// ---------------- helpers ----------------
__device__ __forceinline__ float sp(float v) {           // softplus, stable
    return v > 20.f ? v : log1pf(expf(v));
}

__device__ __forceinline__ ull pk(float lo, float hi) {
    ull r; asm("mov.b64 %0, {%1, %2};" : "=l"(r) : "f"(lo), "f"(hi)); return r;
}
__device__ __forceinline__ void fma2(ull& d, ull a, ull b) {
    asm("fma.rn.f32x2 %0, %1, %2, %0;" : "+l"(d) : "l"(a), "l"(b));
}
__device__ __forceinline__ float2 upk(ull v) {
    float2 f; asm("mov.b64 {%0, %1}, %2;" : "=f"(f.x), "=f"(f.y) : "l"(v)); return f;
}

__device__ __forceinline__ float4 f4fma(float4 acc, float4 a, float4 b) {
    acc.x = fmaf(a.x, b.x, acc.x);
    acc.y = fmaf(a.y, b.y, acc.y);
    acc.z = fmaf(a.z, b.z, acc.z);
    acc.w = fmaf(a.w, b.w, acc.w);
    return acc;
}

// ---------------- kernel 0: effective bias for the gate GEMM ----------------
// ebias[0:64]   = bp[0:64]   + conv_b @ Wp[:, 0:64]
// ebias[64:128] = bp[64:128] + conv_b @ Wp[:, 64:128]
// ebias[128:192]= bs
__global__ void __launch_bounds__(192) ebias_kernel(
    const float* __restrict__ cb, const float* __restrict__ Wp,
    const float* __restrict__ bp, const float* __restrict__ bs,
    float* __restrict__ ebias)
{
    const int n = threadIdx.x;
    if (n < 2 * NN) {
        float s = bp[n];
#pragma unroll 8
        for (int d = 0; d < DD; ++d) s = fmaf(cb[d], Wp[(size_t)d * 2 * NN + n], s);
        ebias[n] = s;
    } else {
        ebias[n] = bs[n - 2 * NN];
    }
}

// ---------------- kernel 1: fused conv + gate GEMMs ----------------
// blockIdx.y selects output:
//   0: Bt = softplus(conv(x) @ Wp[:, :64]  + ebias[0:64])
//   1: Ct = tanh   (conv(x) @ Wp[:, 64:]  + ebias[64:128])
//   2: u  =         x       @ Ws          + ebias[128:192]
// conv(x)[l,d] = w[0,d]x[l-3,d] + w[1,d]x[l-2,d] + w[2,d]x[l-1,d] + w[3,d]x[l,d]
// (conv_b folded into ebias). 64x64 tile, BK=16, 128 threads, 8x4 microtile,
// packed f32x2 FFMA.
__global__ void __launch_bounds__(128) gate_gemm(
    const float* __restrict__ x, const float* __restrict__ cw,
    const float* __restrict__ Wp, const float* __restrict__ Ws,
    const float* __restrict__ ebias,
    float* __restrict__ Bt, float* __restrict__ Ct, float* __restrict__ u)
{
    __shared__ __align__(16) float As[16][64];
    __shared__ __align__(16) float Bs[16][64];

    const int tid = threadIdx.x;
    const int m0  = blockIdx.x * 64;
    const int j   = blockIdx.y;               // 0,1,2

    const float* Bm; int ldb; float* C;
    if (j == 0)      { Bm = Wp;      ldb = 2 * NN; C = Bt; }
    else if (j == 1) { Bm = Wp + NN; ldb = 2 * NN; C = Ct; }
    else             { Bm = Ws;      ldb = NN;     C = u;  }

    // global-load mapping
    const int ar = tid >> 2;             // 0..31: A rows ar, ar+32
    const int ac = (tid & 3) * 4;        // k-offset within tile
    const int br = tid >> 4;             // 0..7: B k-rows br, br+8
    const int bc = (tid & 15) * 4;       // col offset

    // compute mapping
    const int tx = tid & 15, ty = tid >> 4;
    const int r0 = ty * 8, c0 = tx * 4;

    const int rg0 = m0 + ar;             // global A rows for this thread
    const int rg1 = m0 + ar + 32;
    const int l0 = rg0 & (LL - 1);       // position within sequence
    const int l1 = rg1 & (LL - 1);
    const float* xr0 = x + (size_t)rg0 * DD;
    const float* xr1 = x + (size_t)rg1 * DD;

    ull acc[8][2];
#pragma unroll
    for (int i = 0; i < 8; ++i) { acc[i][0] = 0ull; acc[i][1] = 0ull; }

    const float4 z4 = make_float4(0.f, 0.f, 0.f, 0.f);

    for (int kt = 0; kt < DD / 16; ++kt) {
        const int col = kt * 16 + ac;

        // ---- stage A tile (with on-the-fly conv for j<2) ----
        float4 a0, a1;
        if (j < 2) {
            float4 w0 = *(const float4*)&cw[0 * DD + col];
            float4 w1 = *(const float4*)&cw[1 * DD + col];
            float4 w2 = *(const float4*)&cw[2 * DD + col];
            float4 w3 = *(const float4*)&cw[3 * DD + col];
            {
                float4 c0v = *(const float4*)(xr0 + col);
                float4 c1v = (l0 >= 1) ? *(const float4*)(xr0 + col - DD)     : z4;
                float4 c2v = (l0 >= 2) ? *(const float4*)(xr0 + col - 2 * DD) : z4;
                float4 c3v = (l0 >= 3) ? *(const float4*)(xr0 + col - 3 * DD) : z4;
                float4 o = make_float4(0.f, 0.f, 0.f, 0.f);
                o = f4fma(o, w0, c3v); o = f4fma(o, w1, c2v);
                o = f4fma(o, w2, c1v); o = f4fma(o, w3, c0v);
                a0 = o;
            }
            {
                float4 c0v = *(const float4*)(xr1 + col);
                float4 c1v = (l1 >= 1) ? *(const float4*)(xr1 + col - DD)     : z4;
                float4 c2v = (l1 >= 2) ? *(const float4*)(xr1 + col - 2 * DD) : z4;
                float4 c3v = (l1 >= 3) ? *(const float4*)(xr1 + col - 3 * DD) : z4;
                float4 o = make_float4(0.f, 0.f, 0.f, 0.f);
                o = f4fma(o, w0, c3v); o = f4fma(o, w1, c2v);
                o = f4fma(o, w2, c1v); o = f4fma(o, w3, c0v);
                a1 = o;
            }
        } else {
            a0 = *(const float4*)(xr0 + col);
            a1 = *(const float4*)(xr1 + col);
        }
        // A transposed in smem: As[k][m]
        As[ac + 0][ar] = a0.x; As[ac + 1][ar] = a0.y;
        As[ac + 2][ar] = a0.z; As[ac + 3][ar] = a0.w;
        As[ac + 0][ar + 32] = a1.x; As[ac + 1][ar + 32] = a1.y;
        As[ac + 2][ar + 32] = a1.z; As[ac + 3][ar + 32] = a1.w;

        // ---- stage B tile ----
        *(float4*)&Bs[br][bc]     = *(const float4*)&Bm[(size_t)(kt * 16 + br) * ldb + bc];
        *(float4*)&Bs[br + 8][bc] = *(const float4*)&Bm[(size_t)(kt * 16 + br + 8) * ldb + bc];
        __syncthreads();

#pragma unroll
        for (int k = 0; k < 16; ++k) {
            float4 va0 = *(const float4*)&As[k][r0];
            float4 va1 = *(const float4*)&As[k][r0 + 4];
            ull vb01 = *(const ull*)&Bs[k][c0];
            ull vb23 = *(const ull*)&Bs[k][c0 + 2];
            ull d;
            d = pk(va0.x, va0.x); fma2(acc[0][0], d, vb01); fma2(acc[0][1], d, vb23);
            d = pk(va0.y, va0.y); fma2(acc[1][0], d, vb01); fma2(acc[1][1], d, vb23);
            d = pk(va0.z, va0.z); fma2(acc[2][0], d, vb01); fma2(acc[2][1], d, vb23);
            d = pk(va0.w, va0.w); fma2(acc[3][0], d, vb01); fma2(acc[3][1], d, vb23);
            d = pk(va1.x, va1.x); fma2(acc[4][0], d, vb01); fma2(acc[4][1], d, vb23);
            d = pk(va1.y, va1.y); fma2(acc[5][0], d, vb01); fma2(acc[5][1], d, vb23);
            d = pk(va1.z, va1.z); fma2(acc[6][0], d, vb01); fma2(acc[6][1], d, vb23);
            d = pk(va1.w, va1.w); fma2(acc[7][0], d, vb01); fma2(acc[7][1], d, vb23);
        }
        __syncthreads();
    }

    // epilogue: bias + activation
    float4 bb = *(const float4*)&ebias[j * NN + c0];
#pragma unroll
    for (int i = 0; i < 8; ++i) {
        float2 v0 = upk(acc[i][0]);
        float2 v1 = upk(acc[i][1]);
        float4 o = make_float4(v0.x + bb.x, v0.y + bb.y, v1.x + bb.z, v1.y + bb.w);
        if (j == 0) {
            o.x = sp(o.x); o.y = sp(o.y); o.z = sp(o.z); o.w = sp(o.w);
        } else if (j == 1) {
            o.x = tanhf(o.x); o.y = tanhf(o.y); o.z = tanhf(o.z); o.w = tanhf(o.w);
        }
        int row = m0 + r0 + i;
        *(float4*)&C[(size_t)row * NN + c0] = o;
    }
}

// ---------------- kernel 2: fp32 GEMM (output projection) ----------------
// C[m,n] = sum_k A[m,k]*Bm[k,n] + bias[n]. 64x64 tile, BK=16, prefetched.
__global__ void __launch_bounds__(128) gemm64(
    const float* __restrict__ A, int lda,
    const float* __restrict__ Bm, int ldb,
    const float* __restrict__ bias,
    float* __restrict__ C, int ldc,
    int Ktot)
{
    __shared__ __align__(16) float As[16][64];
    __shared__ __align__(16) float Bs[16][64];

    const int tid = threadIdx.x;
    const int m0 = blockIdx.x * 64;
    const int n0 = blockIdx.y * 64;

    const int ar = tid >> 2;
    const int ac = (tid & 3) * 4;
    const int br = tid >> 4;
    const int bc = (tid & 15) * 4;

    const int tx = tid & 15, ty = tid >> 4;
    const int r0 = ty * 8, c0 = tx * 4;

    const int nt = Ktot / 16;
    const float* Ag0 = A + (size_t)(m0 + ar) * lda + ac;
    const float* Ag1 = A + (size_t)(m0 + ar + 32) * lda + ac;
    const float* Bg0 = Bm + (size_t)br * ldb + n0 + bc;
    const float* Bg1 = Bm + (size_t)(br + 8) * ldb + n0 + bc;

    float4 a0 = *(const float4*)Ag0;
    float4 a1 = *(const float4*)Ag1;
    float4 b0 = *(const float4*)Bg0;
    float4 b1 = *(const float4*)Bg1;

    ull acc[8][2];
#pragma unroll
    for (int i = 0; i < 8; ++i) { acc[i][0] = 0ull; acc[i][1] = 0ull; }

    for (int kt = 0; kt < nt; ++kt) {
        As[ac + 0][ar] = a0.x; As[ac + 1][ar] = a0.y;
        As[ac + 2][ar] = a0.z; As[ac + 3][ar] = a0.w;
        As[ac + 0][ar + 32] = a1.x; As[ac + 1][ar + 32] = a1.y;
        As[ac + 2][ar + 32] = a1.z; As[ac + 3][ar + 32] = a1.w;
        *(float4*)&Bs[br][bc]     = b0;
        *(float4*)&Bs[br + 8][bc] = b1;
        __syncthreads();

        if (kt + 1 < nt) {
            a0 = *(const float4*)(Ag0 + (kt + 1) * 16);
            a1 = *(const float4*)(Ag1 + (kt + 1) * 16);
            b0 = *(const float4*)(Bg0 + (size_t)(kt + 1) * 16 * ldb);
            b1 = *(const float4*)(Bg1 + (size_t)(kt + 1) * 16 * ldb);
        }

#pragma unroll
        for (int k = 0; k < 16; ++k) {
            float4 va0 = *(const float4*)&As[k][r0];
            float4 va1 = *(const float4*)&As[k][r0 + 4];
            ull vb01 = *(const ull*)&Bs[k][c0];
            ull vb23 = *(const ull*)&Bs[k][c0 + 2];
            ull d;
            d = pk(va0.x, va0.x); fma2(acc[0][0], d, vb01); fma2(acc[0][1], d, vb23);
            d = pk(va0.y, va0.y); fma2(acc[1][0], d, vb01); fma2(acc[1][1], d, vb23);
            d = pk(va0.z, va0.z); fma2(acc[2][0], d, vb01); fma2(acc[2][1], d, vb23);
            d = pk(va0.w, va0.w); fma2(acc[3][0], d, vb01); fma2(acc[3][1], d, vb23);
            d = pk(va1.x, va1.x); fma2(acc[4][0], d, vb01); fma2(acc[4][1], d, vb23);
            d = pk(va1.y, va1.y); fma2(acc[5][0], d, vb01); fma2(acc[5][1], d, vb23);
            d = pk(va1.z, va1.z); fma2(acc[6][0], d, vb01); fma2(acc[6][1], d, vb23);
            d = pk(va1.w, va1.w); fma2(acc[7][0], d, vb01); fma2(acc[7][1], d, vb23);
        }
        __syncthreads();
    }

    float4 bb = *(const float4*)&bias[n0 + c0];
#pragma unroll
    for (int i = 0; i < 8; ++i) {
        float2 v0 = upk(acc[i][0]);
        float2 v1 = upk(acc[i][1]);
        float4 o = make_float4(v0.x + bb.x, v0.y + bb.y, v1.x + bb.z, v1.y + bb.w);
        int row = m0 + r0 + i;
        *(float4*)&C[(size_t)row * ldc + n0 + c0] = o;
    }
}

// ---------------- scan kernels (chunk-parallel linear recurrence) ----------------
__global__ void __launch_bounds__(64) scan_partial(
    const float* __restrict__ A_log, const float* __restrict__ dt_log,
    const float* __restrict__ u, const float* __restrict__ Bt,
    float* __restrict__ carry)
{
    const int n = threadIdx.x, ch = blockIdx.x, b = blockIdx.y;
    const float dt = sp(dt_log[n]);
    const float decay = 1.f - dt * sp(A_log[n]);
    size_t base = ((size_t)b * LL + (size_t)ch * TCH) * NN + n;
    float s = 0.f;
#pragma unroll 4
    for (int t = 0; t < TCH; ++t) {
        float uu = u[base + (size_t)t * NN];
        float bt = Bt[base + (size_t)t * NN];
        s = fmaf(decay, s, (dt * bt) * uu);
    }
    carry[((size_t)b * NCH + ch) * NN + n] = s;
}

__global__ void __launch_bounds__(256) scan_carry(
    const float* __restrict__ A_log, const float* __restrict__ dt_log,
    float* __restrict__ carry)
{
    const int tid = threadIdx.x;
    const int b = tid >> 6, n = tid & 63;
    const float dt = sp(dt_log[n]);
    const float decay = 1.f - dt * sp(A_log[n]);
    float dp = decay;
#pragma unroll
    for (int i = 0; i < 7; ++i) dp *= dp;          // decay^128 (TCH = 2^7)
    float c = 0.f;
    for (int ch = 0; ch < NCH; ++ch) {
        size_t idx = ((size_t)b * NCH + ch) * NN + n;
        float e = carry[idx];
        carry[idx] = c;                             // carry_in for this chunk
        c = fmaf(dp, c, e);
    }
}

__global__ void __launch_bounds__(64) scan_final(
    const float* __restrict__ A_log, const float* __restrict__ dt_log,
    const float* __restrict__ u, const float* __restrict__ Bt,
    const float* __restrict__ Ct, const float* __restrict__ carry,
    float* __restrict__ y)
{
    const int n = threadIdx.x, ch = blockIdx.x, b = blockIdx.y;
    const float dt = sp(dt_log[n]);
    const float decay = 1.f - dt * sp(A_log[n]);
    size_t base = ((size_t)b * LL + (size_t)ch * TCH) * NN + n;
    float s = carry[((size_t)b * NCH + ch) * NN + n];
#pragma unroll 4
    for (int t = 0; t < TCH; ++t) {
        float uu = u[base + (size_t)t * NN];
        float bt = Bt[base + (size_t)t * NN];
        float ct = Ct[base + (size_t)t * NN];
        s = fmaf(decay, s, (dt * bt) * uu);
        y[base + (size_t)t * NN] = ct * s;
    }
}

// ---------------- launch ----------------
extern "C" void kernel_launch(void* const* d_in, const int* in_sizes, int n_in,
                              void* d_out, int out_size)
{
    const float* x      = (const float*)d_in[0];
    const float* conv_w = (const float*)d_in[1];
    const float* conv_b = (const float*)d_in[2];
    const float* Wp     = (const float*)d_in[3];
    const float* bp     = (const float*)d_in[4];
    const float* Ws     = (const float*)d_in[5];
    const float* bs     = (const float*)d_in[6];
    const float* A_log  = (const float*)d_in[7];
    const float* dt_log = (const float*)d_in[8];
    const float* Wo     = (const float*)d_in[9];
    const float* bo     = (const float*)d_in[10];
    float* out = (float*)d_out;

    float *bt_p, *ct_p, *u_p, *y_p, *carry_p, *ebias_p;
    cudaGetSymbolAddress((void**)&bt_p,    g_Bt);
    cudaGetSymbolAddress((void**)&ct_p,    g_Ct);
    cudaGetSymbolAddress((void**)&u_p,     g_u);
    cudaGetSymbolAddress((void**)&y_p,     g_y);
    cudaGetSymbolAddress((void**)&carry_p, g_carry);
    cudaGetSymbolAddress((void**)&ebias_p, g_ebias);

    const int M = BB * LL;   // 16384

    // 0) effective biases
    ebias_kernel<<<1, 192>>>(conv_b, Wp, bp, bs, ebias_p);

    // 1) fused conv + gate GEMMs (Bt, Ct, u)
    gate_gemm<<<dim3(M / 64, 3), 128>>>(x, conv_w, Wp, Ws, ebias_p, bt_p, ct_p, u_p);

    // 2) chunk-parallel scan -> y
    scan_partial<<<dim3(NCH, BB), 64>>>(A_log, dt_log, u_p, bt_p, carry_p);
    scan_carry<<<1, 256>>>(A_log, dt_log, carry_p);
    scan_final<<<dim3(NCH, BB), 64>>>(A_log, dt_log, u_p, bt_p, ct_p, carry_p, y_p);

    // 3) out = y @ Wo + bo
    gemm64<<<dim3(M / 64, DD / 64), 128>>>(y_p, NN, Wo, DD, bo, out, DD, NN);
}

// round 6
// speedup vs baseline: 1.2297x; 1.2244x over previous
#include <cuda_runtime.h>
#include <cuda_bf16.h>
#include <math.h>
#include <stdint.h>

// Problem dims (fixed by the dataset)
#define BB 4
#define LL 4096
#define DD 1024
#define NN 64
#define MM (BB * LL)
#define NCH 32
#define TCH (LL / NCH)

typedef unsigned int u32;
typedef __nv_bfloat16 bf16;

// ---------------- scratch (device globals: no allocation allowed) ----------------
__device__ bf16 g_convH[MM * DD], g_convL[MM * DD];
__device__ bf16 g_xH[MM * DD],    g_xL[MM * DD];
__device__ bf16 g_WpH[DD * 2 * NN], g_WpL[DD * 2 * NN];   // [1024][128], natural layout
__device__ bf16 g_WsH[DD * NN],     g_WsL[DD * NN];       // [1024][64]
__device__ bf16 g_WoH[NN * DD],     g_WoL[NN * DD];       // [64][1024]
__device__ float g_Bt[MM * NN];
__device__ float g_Ct[MM * NN];
__device__ float g_u [MM * NN];
__device__ bf16  g_yH[MM * NN], g_yL[MM * NN];            // [16384][64]
__device__ float g_carry[BB * NCH * NN];
__device__ float g_ebias[3 * NN];

// ---------------- helpers ----------------
#define SW128(o) ((u32)(o) ^ ((((u32)(o)) >> 3) & 0x70))

__device__ __forceinline__ u32 s2u(const void* p) {
    u32 a;
    asm("{ .reg .u64 t; cvta.to.shared.u64 t, %1; cvt.u32.u64 %0, t; }" : "=r"(a) : "l"(p));
    return a;
}
__device__ __forceinline__ float sp(float v) { return v > 20.f ? v : log1pf(expf(v)); }

#define LDSM4(r, a)                                                                    \
    asm volatile("ldmatrix.sync.aligned.m8n8.x4.shared.b16 {%0,%1,%2,%3}, [%4];"      \
                 : "=r"((r)[0]), "=r"((r)[1]), "=r"((r)[2]), "=r"((r)[3]) : "r"(a))
#define LDSM2T(r, a)                                                                   \
    asm volatile("ldmatrix.sync.aligned.m8n8.x2.trans.shared.b16 {%0,%1}, [%2];"      \
                 : "=r"((r)[0]), "=r"((r)[1]) : "r"(a))
#define MMA(d, a, b)                                                                   \
    asm volatile("mma.sync.aligned.m16n8k16.row.col.f32.bf16.bf16.f32 "               \
                 "{%0,%1,%2,%3}, {%4,%5,%6,%7}, {%8,%9}, {%0,%1,%2,%3};"              \
                 : "+f"((d)[0]), "+f"((d)[1]), "+f"((d)[2]), "+f"((d)[3])             \
                 : "r"((a)[0]), "r"((a)[1]), "r"((a)[2]), "r"((a)[3]),                \
                   "r"((b)[0]), "r"((b)[1]))

__device__ __forceinline__ void split1(float v, bf16& h, bf16& l) {
    h = __float2bfloat16(v);
    l = __float2bfloat16(v - __bfloat162float(h));
}
__device__ __forceinline__ void split_store4(bf16* hi, bf16* lo, size_t idx, float4 v) {
    bf16 h0, l0, h1, l1, h2, l2, h3, l3;
    split1(v.x, h0, l0); split1(v.y, h1, l1);
    split1(v.z, h2, l2); split1(v.w, h3, l3);
    __nv_bfloat162 hp0 = {h0, h1}, hp1 = {h2, h3}, lp0 = {l0, l1}, lp1 = {l2, l3};
    *(uint2*)(hi + idx) = make_uint2(*(u32*)&hp0, *(u32*)&hp1);
    *(uint2*)(lo + idx) = make_uint2(*(u32*)&lp0, *(u32*)&lp1);
}
__device__ __forceinline__ float4 f4fma(float4 acc, float4 a, float4 b) {
    acc.x = fmaf(a.x, b.x, acc.x); acc.y = fmaf(a.y, b.y, acc.y);
    acc.z = fmaf(a.z, b.z, acc.z); acc.w = fmaf(a.w, b.w, acc.w);
    return acc;
}

// ---------------- kernel 0: weight bf16 hi/lo split (natural layout) + ebias -----
__global__ void __launch_bounds__(256) prep_kernel(
    const float* __restrict__ Wp, const float* __restrict__ Ws,
    const float* __restrict__ Wo, const float* __restrict__ cb,
    const float* __restrict__ bp, const float* __restrict__ bs,
    float* __restrict__ ebias)
{
    const int gtid = blockIdx.x * 256 + threadIdx.x;
    const int NT = gridDim.x * 256;

    for (int i = gtid; i < DD * 2 * NN; i += NT) split1(Wp[i], g_WpH[i], g_WpL[i]);
    for (int i = gtid; i < DD * NN;     i += NT) split1(Ws[i], g_WsH[i], g_WsL[i]);
    for (int i = gtid; i < NN * DD;     i += NT) split1(Wo[i], g_WoH[i], g_WoL[i]);

    if (gtid < 2 * NN) {
        float s = bp[gtid];
#pragma unroll 8
        for (int d = 0; d < DD; ++d) s = fmaf(cb[d], Wp[(size_t)d * 2 * NN + gtid], s);
        ebias[gtid] = s;
    } else if (gtid < 3 * NN) {
        ebias[gtid] = bs[gtid - 2 * NN];
    }
}

// ---------------- kernel 1: causal conv (K=4) + bf16 hi/lo conversion ------------
__global__ void __launch_bounds__(256) conv_kernel(
    const float* __restrict__ x, const float* __restrict__ w)
{
    const int S = DD / 4;
    const int d4 = threadIdx.x;
    const int b  = blockIdx.y;
    const int l0 = blockIdx.x * 16;

    const float4* X = (const float4*)x + (size_t)b * LL * S + d4;
    const float4* W = (const float4*)w;

    float4 w0 = W[0 * S + d4], w1 = W[1 * S + d4];
    float4 w2 = W[2 * S + d4], w3 = W[3 * S + d4];

    float4 z = make_float4(0.f, 0.f, 0.f, 0.f);
    float4 xm3 = (l0 - 3 >= 0) ? X[(size_t)(l0 - 3) * S] : z;
    float4 xm2 = (l0 - 2 >= 0) ? X[(size_t)(l0 - 2) * S] : z;
    float4 xm1 = (l0 - 1 >= 0) ? X[(size_t)(l0 - 1) * S] : z;

#pragma unroll
    for (int t = 0; t < 16; ++t) {
        float4 xc = X[(size_t)(l0 + t) * S];
        float4 o = make_float4(0.f, 0.f, 0.f, 0.f);
        o = f4fma(o, w0, xm3); o = f4fma(o, w1, xm2);
        o = f4fma(o, w2, xm1); o = f4fma(o, w3, xc);
        size_t idx = ((size_t)b * LL + l0 + t) * DD + (size_t)d4 * 4;
        split_store4(g_convH, g_convL, idx, o);
        split_store4(g_xH,    g_xL,    idx, xc);
        xm3 = xm2; xm2 = xm1; xm1 = xc;
    }
}

// ---------------- GEMM core: 64x64 tile, BK=64, 4 warps, split-bf16 3-pass -------
// C[m0+.., col] = act( A[m,:] @ B[:, col] + bias[col] ),  A hi/lo, B hi/lo (row-major [k][n])
__device__ __forceinline__ void gemm_core(
    const bf16* __restrict__ Ah, const bf16* __restrict__ Al, int ldaE,
    const bf16* __restrict__ Bh, const bf16* __restrict__ Bl, int ldbE,
    const float* __restrict__ bias, float* __restrict__ C, int ldcE,
    int m0, int Ktiles, int act,
    char* sAh, char* sAl, char* sBh, char* sBl)
{
    const int tid = threadIdx.x;
    const int lane = tid & 31, w = tid >> 5;
    const int mw = (w >> 1) * 32, nw = (w & 1) * 32;

    const u32 aAh = s2u(sAh), aAl = s2u(sAl), aBh = s2u(sBh), aBl = s2u(sBl);

    float acc[2][4][4];
#pragma unroll
    for (int mt = 0; mt < 2; ++mt)
#pragma unroll
        for (int nt = 0; nt < 4; ++nt)
#pragma unroll
            for (int q = 0; q < 4; ++q) acc[mt][nt][q] = 0.f;

    const int arow = lane & 15, acol = (lane >> 4) * 8;  // ldmatrix x4 mapping
    const int brow = lane & 15;                          // ldmatrix x2.trans mapping

    for (int kt = 0; kt < Ktiles; ++kt) {
        // ---- stage 64x64 bf16 tiles (hi+lo for A and B), SW128 swizzle ----
#pragma unroll
        for (int i = 0; i < 4; ++i) {
            int c = i * 128 + tid;          // chunk 0..511 (16B each)
            int r = c >> 3, cb = (c & 7) * 16;
            u32 sw = SW128(r * 128 + cb);
            const char* pA = (const char*)Ah + ((size_t)(m0 + r) * ldaE + kt * 64) * 2 + cb;
            const char* pAl2 = (const char*)Al + ((size_t)(m0 + r) * ldaE + kt * 64) * 2 + cb;
            *(uint4*)(sAh + sw) = *(const uint4*)pA;
            *(uint4*)(sAl + sw) = *(const uint4*)pAl2;
            const char* pB = (const char*)Bh + ((size_t)(kt * 64 + r) * ldbE) * 2 + cb;
            const char* pBl2 = (const char*)Bl + ((size_t)(kt * 64 + r) * ldbE) * 2 + cb;
            *(uint4*)(sBh + sw) = *(const uint4*)pB;
            *(uint4*)(sBl + sw) = *(const uint4*)pBl2;
        }
        __syncthreads();

        // ---- compute: 4 k-steps of 16 ----
#pragma unroll
        for (int ks = 0; ks < 4; ++ks) {
            u32 ah[2][4], al[2][4], bh[4][2], bl[4][2];
#pragma unroll
            for (int mt = 0; mt < 2; ++mt) {
                u32 off = SW128((mw + mt * 16 + arow) * 128 + (ks * 16 + acol) * 2);
                LDSM4(ah[mt], aAh + off);
                LDSM4(al[mt], aAl + off);
            }
#pragma unroll
            for (int nt = 0; nt < 4; ++nt) {
                u32 off = SW128((ks * 16 + brow) * 128 + (nw + nt * 8) * 2);
                LDSM2T(bh[nt], aBh + off);
                LDSM2T(bl[nt], aBl + off);
            }
#pragma unroll
            for (int mt = 0; mt < 2; ++mt)
#pragma unroll
                for (int nt = 0; nt < 4; ++nt) {
                    MMA(acc[mt][nt], ah[mt], bh[nt]);
                    MMA(acc[mt][nt], ah[mt], bl[nt]);
                    MMA(acc[mt][nt], al[mt], bh[nt]);
                }
        }
        __syncthreads();
    }

    // ---- epilogue: bias + activation ----
#pragma unroll
    for (int mt = 0; mt < 2; ++mt)
#pragma unroll
        for (int nt = 0; nt < 4; ++nt) {
            int r0 = m0 + mw + mt * 16 + (lane >> 2);
            int col = nw + nt * 8 + 2 * (lane & 3);
            float b0v = bias[col], b1v = bias[col + 1];
            float vx = acc[mt][nt][0] + b0v, vy = acc[mt][nt][1] + b1v;
            float vz = acc[mt][nt][2] + b0v, vw = acc[mt][nt][3] + b1v;
            if (act == 1) { vx = sp(vx); vy = sp(vy); vz = sp(vz); vw = sp(vw); }
            else if (act == 2) { vx = tanhf(vx); vy = tanhf(vy); vz = tanhf(vz); vw = tanhf(vw); }
            *(float2*)&C[(size_t)r0 * ldcE + col] = make_float2(vx, vy);
            *(float2*)&C[(size_t)(r0 + 8) * ldcE + col] = make_float2(vz, vw);
        }
}

// ---------------- kernel 2: gate GEMMs (Bt, Ct, u) ----------------
__global__ void __launch_bounds__(128) tc_gate(
    const float* __restrict__ ebias,
    float* __restrict__ Bt, float* __restrict__ Ct, float* __restrict__ u)
{
    __shared__ __align__(1024) char sAh[8192], sAl[8192], sBh[8192], sBl[8192];
    const int m0 = blockIdx.x * 64;
    const int j = blockIdx.y;

    if (j == 0) {
        gemm_core(g_convH, g_convL, DD, g_WpH, g_WpL, 2 * NN,
                  ebias, Bt, NN, m0, DD / 64, 1, sAh, sAl, sBh, sBl);
    } else if (j == 1) {
        gemm_core(g_convH, g_convL, DD, g_WpH + NN, g_WpL + NN, 2 * NN,
                  ebias + NN, Ct, NN, m0, DD / 64, 2, sAh, sAl, sBh, sBl);
    } else {
        gemm_core(g_xH, g_xL, DD, g_WsH, g_WsL, NN,
                  ebias + 2 * NN, u, NN, m0, DD / 64, 0, sAh, sAl, sBh, sBl);
    }
}

// ---------------- kernel 3: output GEMM (out = y @ Wo + bo) ----------------
__global__ void __launch_bounds__(128) tc_out(
    const float* __restrict__ bo, float* __restrict__ out)
{
    __shared__ __align__(1024) char sAh[8192], sAl[8192], sBh[8192], sBl[8192];
    const int m0 = blockIdx.x * 64;
    const int n0 = blockIdx.y * 64;
    gemm_core(g_yH, g_yL, NN, g_WoH + n0, g_WoL + n0, DD,
              bo + n0, out + n0, DD, m0, 1, 0, sAh, sAl, sBh, sBl);
}

// ---------------- scan kernels (chunk-parallel linear recurrence) ----------------
__global__ void __launch_bounds__(64) scan_partial(
    const float* __restrict__ A_log, const float* __restrict__ dt_log,
    const float* __restrict__ u, const float* __restrict__ Bt,
    float* __restrict__ carry)
{
    const int n = threadIdx.x, ch = blockIdx.x, b = blockIdx.y;
    const float dt = sp(dt_log[n]);
    const float decay = 1.f - dt * sp(A_log[n]);
    size_t base = ((size_t)b * LL + (size_t)ch * TCH) * NN + n;
    float s = 0.f;
#pragma unroll 4
    for (int t = 0; t < TCH; ++t) {
        float uu = u[base + (size_t)t * NN];
        float bt = Bt[base + (size_t)t * NN];
        s = fmaf(decay, s, (dt * bt) * uu);
    }
    carry[((size_t)b * NCH + ch) * NN + n] = s;
}

__global__ void __launch_bounds__(256) scan_carry(
    const float* __restrict__ A_log, const float* __restrict__ dt_log,
    float* __restrict__ carry)
{
    const int tid = threadIdx.x;
    const int b = tid >> 6, n = tid & 63;
    const float dt = sp(dt_log[n]);
    const float decay = 1.f - dt * sp(A_log[n]);
    float dp = decay;
#pragma unroll
    for (int i = 0; i < 7; ++i) dp *= dp;          // decay^128
    float c = 0.f;
    for (int ch = 0; ch < NCH; ++ch) {
        size_t idx = ((size_t)b * NCH + ch) * NN + n;
        float e = carry[idx];
        carry[idx] = c;
        c = fmaf(dp, c, e);
    }
}

__global__ void __launch_bounds__(64) scan_final(
    const float* __restrict__ A_log, const float* __restrict__ dt_log,
    const float* __restrict__ u, const float* __restrict__ Bt,
    const float* __restrict__ Ct, const float* __restrict__ carry)
{
    const int n = threadIdx.x, ch = blockIdx.x, b = blockIdx.y;
    const float dt = sp(dt_log[n]);
    const float decay = 1.f - dt * sp(A_log[n]);
    size_t base = ((size_t)b * LL + (size_t)ch * TCH) * NN + n;
    float s = carry[((size_t)b * NCH + ch) * NN + n];
#pragma unroll 4
    for (int t = 0; t < TCH; ++t) {
        size_t idx = base + (size_t)t * NN;
        float uu = u[idx];
        float bt = Bt[idx];
        float ct = Ct[idx];
        s = fmaf(decay, s, (dt * bt) * uu);
        float yv = ct * s;
        split1(yv, g_yH[idx], g_yL[idx]);
    }
}

// ---------------- launch ----------------
extern "C" void kernel_launch(void* const* d_in, const int* in_sizes, int n_in,
                              void* d_out, int out_size)
{
    const float* x      = (const float*)d_in[0];
    const float* conv_w = (const float*)d_in[1];
    const float* conv_b = (const float*)d_in[2];
    const float* Wp     = (const float*)d_in[3];
    const float* bp     = (const float*)d_in[4];
    const float* Ws     = (const float*)d_in[5];
    const float* bs     = (const float*)d_in[6];
    const float* A_log  = (const float*)d_in[7];
    const float* dt_log = (const float*)d_in[8];
    const float* Wo     = (const float*)d_in[9];
    const float* bo     = (const float*)d_in[10];
    float* out = (float*)d_out;

    float *bt_p, *ct_p, *u_p, *carry_p, *ebias_p;
    cudaGetSymbolAddress((void**)&bt_p,    g_Bt);
    cudaGetSymbolAddress((void**)&ct_p,    g_Ct);
    cudaGetSymbolAddress((void**)&u_p,     g_u);
    cudaGetSymbolAddress((void**)&carry_p, g_carry);
    cudaGetSymbolAddress((void**)&ebias_p, g_ebias);

    // 0) weights -> bf16 hi/lo, effective biases
    prep_kernel<<<64, 256>>>(Wp, Ws, Wo, conv_b, bp, bs, ebias_p);

    // 1) causal conv + bf16 hi/lo conversion of conv and x
    conv_kernel<<<dim3(LL / 16, BB), 256>>>(x, conv_w);

    // 2) tensor-core gate GEMMs: Bt, Ct, u   (grid 256x3 = 768 blocks)
    tc_gate<<<dim3(MM / 64, 3), 128>>>(ebias_p, bt_p, ct_p, u_p);

    // 3) chunk-parallel scan -> y (bf16 hi/lo)
    scan_partial<<<dim3(NCH, BB), 64>>>(A_log, dt_log, u_p, bt_p, carry_p);
    scan_carry<<<1, 256>>>(A_log, dt_log, carry_p);
    scan_final<<<dim3(NCH, BB), 64>>>(A_log, dt_log, u_p, bt_p, ct_p, carry_p);

    // 4) tensor-core output GEMM: out = y @ Wo + bo   (grid 256x16 = 4096 blocks)
    tc_out<<<dim3(MM / 64, DD / 16 / 4), 128>>>(bo, out);
}

// round 7
// speedup vs baseline: 1.6238x; 1.3204x over previous
#include <cuda_runtime.h>
#include <cuda_bf16.h>
#include <math.h>
#include <stdint.h>

// Problem dims (fixed by the dataset)
#define BB 4
#define LL 4096
#define DD 1024
#define NN 64
#define MM (BB * LL)
#define NCH 128
#define TCH (LL / NCH)    // 32

typedef unsigned int u32;
typedef __nv_bfloat16 bf16;

// ---------------- scratch (device globals: no allocation allowed) ----------------
__device__ bf16 g_WpH[DD * 2 * NN], g_WpL[DD * 2 * NN];   // [1024][128], natural layout
__device__ bf16 g_WsH[DD * NN],     g_WsL[DD * NN];       // [1024][64]
__device__ bf16 g_WoH[NN * DD],     g_WoL[NN * DD];       // [64][1024]
__device__ float g_Bt[MM * NN];
__device__ float g_Ct[MM * NN];
__device__ float g_u [MM * NN];
__device__ bf16  g_yH[MM * NN], g_yL[MM * NN];            // [16384][64]
__device__ float g_carry[BB * NCH * NN];
__device__ float g_ebias[3 * NN];

// ---------------- helpers ----------------
#define SW128(o) ((u32)(o) ^ ((((u32)(o)) >> 3) & 0x70))

__device__ __forceinline__ u32 s2u(const void* p) {
    u32 a;
    asm("{ .reg .u64 t; cvta.to.shared.u64 t, %1; cvt.u32.u64 %0, t; }" : "=r"(a) : "l"(p));
    return a;
}
__device__ __forceinline__ float sp(float v) { return v > 20.f ? v : log1pf(expf(v)); }

#define LDSM4(r, a)                                                                    \
    asm volatile("ldmatrix.sync.aligned.m8n8.x4.shared.b16 {%0,%1,%2,%3}, [%4];"      \
                 : "=r"((r)[0]), "=r"((r)[1]), "=r"((r)[2]), "=r"((r)[3]) : "r"(a))
#define LDSM2T(r, a)                                                                   \
    asm volatile("ldmatrix.sync.aligned.m8n8.x2.trans.shared.b16 {%0,%1}, [%2];"      \
                 : "=r"((r)[0]), "=r"((r)[1]) : "r"(a))
#define MMA(d, a, b)                                                                   \
    asm volatile("mma.sync.aligned.m16n8k16.row.col.f32.bf16.bf16.f32 "               \
                 "{%0,%1,%2,%3}, {%4,%5,%6,%7}, {%8,%9}, {%0,%1,%2,%3};"              \
                 : "+f"((d)[0]), "+f"((d)[1]), "+f"((d)[2]), "+f"((d)[3])             \
                 : "r"((a)[0]), "r"((a)[1]), "r"((a)[2]), "r"((a)[3]),                \
                   "r"((b)[0]), "r"((b)[1]))

__device__ __forceinline__ void split1(float v, bf16& h, bf16& l) {
    h = __float2bfloat16(v);
    l = __float2bfloat16(v - __bfloat162float(h));
}
// split a float4 into 8B hi + 8B lo, store to smem byte pointers
__device__ __forceinline__ void split_store8(char* hiP, char* loP, float4 v) {
    bf16 h0, l0, h1, l1, h2, l2, h3, l3;
    split1(v.x, h0, l0); split1(v.y, h1, l1);
    split1(v.z, h2, l2); split1(v.w, h3, l3);
    __nv_bfloat162 hp0 = {h0, h1}, hp1 = {h2, h3};
    __nv_bfloat162 lp0 = {l0, l1}, lp1 = {l2, l3};
    *(uint2*)hiP = make_uint2(*(u32*)&hp0, *(u32*)&hp1);
    *(uint2*)loP = make_uint2(*(u32*)&lp0, *(u32*)&lp1);
}
__device__ __forceinline__ float4 f4fma(float4 acc, float4 a, float4 b) {
    acc.x = fmaf(a.x, b.x, acc.x); acc.y = fmaf(a.y, b.y, acc.y);
    acc.z = fmaf(a.z, b.z, acc.z); acc.w = fmaf(a.w, b.w, acc.w);
    return acc;
}

// ---------------- kernel 0: weight bf16 hi/lo split (natural layout) + ebias -----
__global__ void __launch_bounds__(256) prep_kernel(
    const float* __restrict__ Wp, const float* __restrict__ Ws,
    const float* __restrict__ Wo, const float* __restrict__ cb,
    const float* __restrict__ bp, const float* __restrict__ bs,
    float* __restrict__ ebias)
{
    const int gtid = blockIdx.x * 256 + threadIdx.x;
    const int NT = gridDim.x * 256;

    for (int i = gtid; i < DD * 2 * NN; i += NT) split1(Wp[i], g_WpH[i], g_WpL[i]);
    for (int i = gtid; i < DD * NN;     i += NT) split1(Ws[i], g_WsH[i], g_WsL[i]);
    for (int i = gtid; i < NN * DD;     i += NT) split1(Wo[i], g_WoH[i], g_WoL[i]);

    if (gtid < 2 * NN) {
        float s = bp[gtid];
#pragma unroll 8
        for (int d = 0; d < DD; ++d) s = fmaf(cb[d], Wp[(size_t)d * 2 * NN + gtid], s);
        ebias[gtid] = s;
    } else if (gtid < 3 * NN) {
        ebias[gtid] = bs[gtid - 2 * NN];
    }
}

// ---------------- kernel 1: fused conv + gate GEMM (Bt|Ct), N=128 ----------------
// 256 threads (8 warps, 2x4 warp grid; warp tile 32x32). M-tile 64, BK=64.
// A-tile = conv(x) computed in staging (raw x tile + 3 halo rows in smem).
// dynamic smem layout:
//   sX  @ 0      : 67 rows x 64 fp32 (256B rows)                  17408 B (padded)
//   sAh @ 17408  : 64x64 bf16 SW128                                8192 B
//   sAl @ 25600  :                                                 8192 B
//   sBh @ 33792  : 64 x 128 bf16, two 64-col panels, SW128        16384 B
//   sBl @ 50176  :                                                16384 B
#define GT_SX  0
#define GT_AH  17408
#define GT_AL  25600
#define GT_BH  33792
#define GT_BL  50176
#define GT_SMEM 66560

__global__ void __launch_bounds__(256) tc_gate(
    const float* __restrict__ x, const float* __restrict__ cw,
    const float* __restrict__ ebias,
    float* __restrict__ Bt, float* __restrict__ Ct)
{
    extern __shared__ char dsm[];
    char* sX  = dsm + GT_SX;
    char* sAh = dsm + GT_AH;
    char* sAl = dsm + GT_AL;
    char* sBh = dsm + GT_BH;
    char* sBl = dsm + GT_BL;

    const int tid = threadIdx.x;
    const int lane = tid & 31, w = tid >> 5;
    const int mw = (w >> 2) * 32, nw = (w & 3) * 32;
    const int m0 = blockIdx.x * 64;
    const int l0 = m0 & (LL - 1);
    const bool seqstart = (l0 == 0);

    const u32 aAh = s2u(sAh), aAl = s2u(sAl), aBh = s2u(sBh), aBl = s2u(sBl);

    float acc[2][4][4];
#pragma unroll
    for (int mt = 0; mt < 2; ++mt)
#pragma unroll
        for (int nt = 0; nt < 4; ++nt)
#pragma unroll
            for (int q = 0; q < 4; ++q) acc[mt][nt][q] = 0.f;

    const int arow = lane & 15, acol = (lane >> 4) * 8;
    const int brow = lane & 15;

    for (int kt = 0; kt < DD / 64; ++kt) {
        // ---- phase 1: raw x rows (m0-3 .. m0+63) x 64 cols -> sX; B tiles ----
        for (int i = tid; i < 67 * 16; i += 256) {
            int rr = i >> 4, ch = i & 15;
            float4 v;
            if (seqstart && rr < 3) v = make_float4(0.f, 0.f, 0.f, 0.f);
            else v = *(const float4*)(x + (size_t)(m0 - 3 + rr) * DD + kt * 64 + ch * 4);
            *(float4*)(sX + rr * 256 + ch * 16) = v;
        }
#pragma unroll
        for (int i = tid; i < 64 * 16; i += 256) {     // B: Wp rows kt*64.., 128 cols
            int r = i >> 4, ch = i & 15;
            size_t gb = (size_t)(kt * 64 + r) * 256 + ch * 16;
            int panel = ch >> 3;
            u32 sw = (u32)panel * 8192 + SW128(r * 128 + (ch & 7) * 16);
            *(uint4*)(sBh + sw) = *(const uint4*)((const char*)g_WpH + gb);
            *(uint4*)(sBl + sw) = *(const uint4*)((const char*)g_WpL + gb);
        }
        __syncthreads();

        // ---- phase 2: conv + split -> sAh/sAl ----
#pragma unroll
        for (int i = tid; i < 64 * 16; i += 256) {
            int r = i >> 4, ch = i & 15;
            float4 xm3 = *(const float4*)(sX + (r + 0) * 256 + ch * 16);
            float4 xm2 = *(const float4*)(sX + (r + 1) * 256 + ch * 16);
            float4 xm1 = *(const float4*)(sX + (r + 2) * 256 + ch * 16);
            float4 xc  = *(const float4*)(sX + (r + 3) * 256 + ch * 16);
            int dcol = kt * 64 + ch * 4;
            float4 w0 = *(const float4*)(cw + 0 * DD + dcol);
            float4 w1 = *(const float4*)(cw + 1 * DD + dcol);
            float4 w2 = *(const float4*)(cw + 2 * DD + dcol);
            float4 w3 = *(const float4*)(cw + 3 * DD + dcol);
            float4 o = make_float4(0.f, 0.f, 0.f, 0.f);
            o = f4fma(o, w0, xm3); o = f4fma(o, w1, xm2);
            o = f4fma(o, w2, xm1); o = f4fma(o, w3, xc);
            u32 sw = SW128(r * 128 + ch * 8);
            split_store8(sAh + sw, sAl + sw, o);
        }
        __syncthreads();

        // ---- compute: 4 k-steps of 16 ----
#pragma unroll
        for (int ks = 0; ks < 4; ++ks) {
            u32 ah[2][4], al[2][4], bh[4][2], bl[4][2];
#pragma unroll
            for (int mt = 0; mt < 2; ++mt) {
                u32 off = SW128((mw + mt * 16 + arow) * 128 + (ks * 16 + acol) * 2);
                LDSM4(ah[mt], aAh + off);
                LDSM4(al[mt], aAl + off);
            }
#pragma unroll
            for (int nt = 0; nt < 4; ++nt) {
                int col = nw + nt * 8;
                u32 off = (u32)(col >> 6) * 8192 +
                          SW128((ks * 16 + brow) * 128 + (col & 63) * 2);
                LDSM2T(bh[nt], aBh + off);
                LDSM2T(bl[nt], aBl + off);
            }
#pragma unroll
            for (int mt = 0; mt < 2; ++mt)
#pragma unroll
                for (int nt = 0; nt < 4; ++nt) {
                    MMA(acc[mt][nt], ah[mt], bh[nt]);
                    MMA(acc[mt][nt], ah[mt], bl[nt]);
                    MMA(acc[mt][nt], al[mt], bh[nt]);
                }
        }
        __syncthreads();
    }

    // ---- epilogue: bias + activation; cols<64 -> softplus->Bt, else tanh->Ct ----
#pragma unroll
    for (int mt = 0; mt < 2; ++mt)
#pragma unroll
        for (int nt = 0; nt < 4; ++nt) {
            int r0 = m0 + mw + mt * 16 + (lane >> 2);
            int col = nw + nt * 8 + 2 * (lane & 3);
            float b0v = ebias[col], b1v = ebias[col + 1];
            float vx = acc[mt][nt][0] + b0v, vy = acc[mt][nt][1] + b1v;
            float vz = acc[mt][nt][2] + b0v, vw = acc[mt][nt][3] + b1v;
            if (col < 64) {
                vx = sp(vx); vy = sp(vy); vz = sp(vz); vw = sp(vw);
                *(float2*)&g_Bt[(size_t)r0 * NN + col] = make_float2(vx, vy);
                *(float2*)&g_Bt[(size_t)(r0 + 8) * NN + col] = make_float2(vz, vw);
            } else {
                vx = tanhf(vx); vy = tanhf(vy); vz = tanhf(vz); vw = tanhf(vw);
                *(float2*)&g_Ct[(size_t)r0 * NN + col - 64] = make_float2(vx, vy);
                *(float2*)&g_Ct[(size_t)(r0 + 8) * NN + col - 64] = make_float2(vz, vw);
            }
        }
    (void)Bt; (void)Ct;
}

// ---------------- kernel 2: u = x @ Ws + bs (N=64, A split on the fly) -----------
__global__ void __launch_bounds__(128) tc_u(
    const float* __restrict__ x, const float* __restrict__ ebias,
    float* __restrict__ u)
{
    __shared__ __align__(1024) char sAh[8192], sAl[8192], sBh[8192], sBl[8192];
    const int tid = threadIdx.x;
    const int lane = tid & 31, w = tid >> 5;
    const int mw = (w >> 1) * 32, nw = (w & 1) * 32;
    const int m0 = blockIdx.x * 64;

    const u32 aAh = s2u(sAh), aAl = s2u(sAl), aBh = s2u(sBh), aBl = s2u(sBl);

    float acc[2][4][4];
#pragma unroll
    for (int mt = 0; mt < 2; ++mt)
#pragma unroll
        for (int nt = 0; nt < 4; ++nt)
#pragma unroll
            for (int q = 0; q < 4; ++q) acc[mt][nt][q] = 0.f;

    const int arow = lane & 15, acol = (lane >> 4) * 8;
    const int brow = lane & 15;

    for (int kt = 0; kt < DD / 64; ++kt) {
        // stage A: raw fp32 x -> split bf16 hi/lo
#pragma unroll
        for (int i = tid; i < 64 * 16; i += 128) {
            int r = i >> 4, ch = i & 15;
            float4 v = *(const float4*)(x + (size_t)(m0 + r) * DD + kt * 64 + ch * 4);
            u32 sw = SW128(r * 128 + ch * 8);
            split_store8(sAh + sw, sAl + sw, v);
        }
        // stage B: Ws rows kt*64.., 64 cols (128B rows)
#pragma unroll
        for (int i = tid; i < 64 * 8; i += 128) {
            int r = i >> 3, ch = i & 7;
            size_t gb = (size_t)(kt * 64 + r) * 128 + ch * 16;
            u32 sw = SW128(r * 128 + ch * 16);
            *(uint4*)(sBh + sw) = *(const uint4*)((const char*)g_WsH + gb);
            *(uint4*)(sBl + sw) = *(const uint4*)((const char*)g_WsL + gb);
        }
        __syncthreads();

#pragma unroll
        for (int ks = 0; ks < 4; ++ks) {
            u32 ah[2][4], al[2][4], bh[4][2], bl[4][2];
#pragma unroll
            for (int mt = 0; mt < 2; ++mt) {
                u32 off = SW128((mw + mt * 16 + arow) * 128 + (ks * 16 + acol) * 2);
                LDSM4(ah[mt], aAh + off);
                LDSM4(al[mt], aAl + off);
            }
#pragma unroll
            for (int nt = 0; nt < 4; ++nt) {
                u32 off = SW128((ks * 16 + brow) * 128 + (nw + nt * 8) * 2);
                LDSM2T(bh[nt], aBh + off);
                LDSM2T(bl[nt], aBl + off);
            }
#pragma unroll
            for (int mt = 0; mt < 2; ++mt)
#pragma unroll
                for (int nt = 0; nt < 4; ++nt) {
                    MMA(acc[mt][nt], ah[mt], bh[nt]);
                    MMA(acc[mt][nt], ah[mt], bl[nt]);
                    MMA(acc[mt][nt], al[mt], bh[nt]);
                }
        }
        __syncthreads();
    }

#pragma unroll
    for (int mt = 0; mt < 2; ++mt)
#pragma unroll
        for (int nt = 0; nt < 4; ++nt) {
            int r0 = m0 + mw + mt * 16 + (lane >> 2);
            int col = nw + nt * 8 + 2 * (lane & 3);
            float b0v = ebias[2 * NN + col], b1v = ebias[2 * NN + col + 1];
            *(float2*)&u[(size_t)r0 * NN + col] =
                make_float2(acc[mt][nt][0] + b0v, acc[mt][nt][1] + b1v);
            *(float2*)&u[(size_t)(r0 + 8) * NN + col] =
                make_float2(acc[mt][nt][2] + b0v, acc[mt][nt][3] + b1v);
        }
}

// ---------------- kernel 3: out = y @ Wo + bo (N-tile 128, K=64) -----------------
__global__ void __launch_bounds__(256) tc_out(
    const float* __restrict__ bo, float* __restrict__ out)
{
    __shared__ __align__(1024) char sAh[8192], sAl[8192], sBh[16384], sBl[16384];
    const int tid = threadIdx.x;
    const int lane = tid & 31, w = tid >> 5;
    const int mw = (w >> 2) * 32, nw = (w & 3) * 32;
    const int m0 = blockIdx.x * 64;
    const int n0 = blockIdx.y * 128;

    const u32 aAh = s2u(sAh), aAl = s2u(sAl), aBh = s2u(sBh), aBl = s2u(sBl);

    // stage A: y rows m0.. (128B rows)
#pragma unroll
    for (int i = tid; i < 64 * 8; i += 256) {
        int r = i >> 3, ch = i & 7;
        size_t gb = (size_t)(m0 + r) * 128 + ch * 16;
        u32 sw = SW128(r * 128 + ch * 16);
        *(uint4*)(sAh + sw) = *(const uint4*)((const char*)g_yH + gb);
        *(uint4*)(sAl + sw) = *(const uint4*)((const char*)g_yL + gb);
    }
    // stage B: Wo rows 0..63 (k), cols n0..n0+127 (row bytes 2048)
#pragma unroll
    for (int i = tid; i < 64 * 16; i += 256) {
        int r = i >> 4, ch = i & 15;
        size_t gb = (size_t)r * 2048 + (size_t)n0 * 2 + ch * 16;
        int panel = ch >> 3;
        u32 sw = (u32)panel * 8192 + SW128(r * 128 + (ch & 7) * 16);
        *(uint4*)(sBh + sw) = *(const uint4*)((const char*)g_WoH + gb);
        *(uint4*)(sBl + sw) = *(const uint4*)((const char*)g_WoL + gb);
    }
    __syncthreads();

    float acc[2][4][4];
#pragma unroll
    for (int mt = 0; mt < 2; ++mt)
#pragma unroll
        for (int nt = 0; nt < 4; ++nt)
#pragma unroll
            for (int q = 0; q < 4; ++q) acc[mt][nt][q] = 0.f;

    const int arow = lane & 15, acol = (lane >> 4) * 8;
    const int brow = lane & 15;

#pragma unroll
    for (int ks = 0; ks < 4; ++ks) {
        u32 ah[2][4], al[2][4], bh[4][2], bl[4][2];
#pragma unroll
        for (int mt = 0; mt < 2; ++mt) {
            u32 off = SW128((mw + mt * 16 + arow) * 128 + (ks * 16 + acol) * 2);
            LDSM4(ah[mt], aAh + off);
            LDSM4(al[mt], aAl + off);
        }
#pragma unroll
        for (int nt = 0; nt < 4; ++nt) {
            int col = nw + nt * 8;
            u32 off = (u32)(col >> 6) * 8192 +
                      SW128((ks * 16 + brow) * 128 + (col & 63) * 2);
            LDSM2T(bh[nt], aBh + off);
            LDSM2T(bl[nt], aBl + off);
        }
#pragma unroll
        for (int mt = 0; mt < 2; ++mt)
#pragma unroll
            for (int nt = 0; nt < 4; ++nt) {
                MMA(acc[mt][nt], ah[mt], bh[nt]);
                MMA(acc[mt][nt], ah[mt], bl[nt]);
                MMA(acc[mt][nt], al[mt], bh[nt]);
            }
    }

#pragma unroll
    for (int mt = 0; mt < 2; ++mt)
#pragma unroll
        for (int nt = 0; nt < 4; ++nt) {
            int r0 = m0 + mw + mt * 16 + (lane >> 2);
            int col = n0 + nw + nt * 8 + 2 * (lane & 3);
            float b0v = bo[col], b1v = bo[col + 1];
            *(float2*)&out[(size_t)r0 * DD + col] =
                make_float2(acc[mt][nt][0] + b0v, acc[mt][nt][1] + b1v);
            *(float2*)&out[(size_t)(r0 + 8) * DD + col] =
                make_float2(acc[mt][nt][2] + b0v, acc[mt][nt][3] + b1v);
        }
}

// ---------------- scan kernels (chunk-parallel linear recurrence) ----------------
// 256-thread blocks handle 4 chunks each; grid (NCH/4, BB).
__global__ void __launch_bounds__(256) scan_partial(
    const float* __restrict__ A_log, const float* __restrict__ dt_log,
    const float* __restrict__ u, const float* __restrict__ Bt,
    float* __restrict__ carry)
{
    const int n = threadIdx.x & 63;
    const int ch = blockIdx.x * 4 + (threadIdx.x >> 6);
    const int b = blockIdx.y;
    const float dt = sp(dt_log[n]);
    const float decay = 1.f - dt * sp(A_log[n]);
    size_t base = ((size_t)b * LL + (size_t)ch * TCH) * NN + n;
    float s = 0.f;
#pragma unroll 4
    for (int t = 0; t < TCH; ++t) {
        float uu = u[base + (size_t)t * NN];
        float bt = Bt[base + (size_t)t * NN];
        s = fmaf(decay, s, (dt * bt) * uu);
    }
    carry[((size_t)b * NCH + ch) * NN + n] = s;
}

// single block, all carries resident in smem (BB*NCH*NN floats = 128 KB)
__global__ void __launch_bounds__(256) scan_carry(
    const float* __restrict__ A_log, const float* __restrict__ dt_log,
    float* __restrict__ carry)
{
    extern __shared__ float sc[];
    const int tid = threadIdx.x;
    const int total = BB * NCH * NN;
    for (int i = tid * 4; i < total; i += 256 * 4)
        *(float4*)&sc[i] = *(const float4*)&carry[i];
    __syncthreads();

    const int b = tid >> 6, n = tid & 63;
    const float dt = sp(dt_log[n]);
    const float decay = 1.f - dt * sp(A_log[n]);
    float dp = decay;
#pragma unroll
    for (int i = 0; i < 5; ++i) dp *= dp;          // decay^32 (TCH = 2^5)
    float c = 0.f;
#pragma unroll 4
    for (int ch = 0; ch < NCH; ++ch) {
        int idx = (b * NCH + ch) * NN + n;
        float e = sc[idx];
        sc[idx] = c;                               // carry_in for this chunk
        c = fmaf(dp, c, e);
    }
    __syncthreads();
    for (int i = tid * 4; i < total; i += 256 * 4)
        *(float4*)&carry[i] = *(const float4*)&sc[i];
}

__global__ void __launch_bounds__(256) scan_final(
    const float* __restrict__ A_log, const float* __restrict__ dt_log,
    const float* __restrict__ u, const float* __restrict__ Bt,
    const float* __restrict__ Ct, const float* __restrict__ carry)
{
    const int n = threadIdx.x & 63;
    const int ch = blockIdx.x * 4 + (threadIdx.x >> 6);
    const int b = blockIdx.y;
    const float dt = sp(dt_log[n]);
    const float decay = 1.f - dt * sp(A_log[n]);
    size_t base = ((size_t)b * LL + (size_t)ch * TCH) * NN + n;
    float s = carry[((size_t)b * NCH + ch) * NN + n];
#pragma unroll 4
    for (int t = 0; t < TCH; ++t) {
        size_t idx = base + (size_t)t * NN;
        float uu = u[idx];
        float bt = Bt[idx];
        float ct = Ct[idx];
        s = fmaf(decay, s, (dt * bt) * uu);
        float yv = ct * s;
        split1(yv, g_yH[idx], g_yL[idx]);
    }
}

// ---------------- launch ----------------
extern "C" void kernel_launch(void* const* d_in, const int* in_sizes, int n_in,
                              void* d_out, int out_size)
{
    const float* x      = (const float*)d_in[0];
    const float* conv_w = (const float*)d_in[1];
    const float* conv_b = (const float*)d_in[2];
    const float* Wp     = (const float*)d_in[3];
    const float* bp     = (const float*)d_in[4];
    const float* Ws     = (const float*)d_in[5];
    const float* bs     = (const float*)d_in[6];
    const float* A_log  = (const float*)d_in[7];
    const float* dt_log = (const float*)d_in[8];
    const float* Wo     = (const float*)d_in[9];
    const float* bo     = (const float*)d_in[10];
    float* out = (float*)d_out;

    float *bt_p, *ct_p, *u_p, *carry_p, *ebias_p;
    cudaGetSymbolAddress((void**)&bt_p,    g_Bt);
    cudaGetSymbolAddress((void**)&ct_p,    g_Ct);
    cudaGetSymbolAddress((void**)&u_p,     g_u);
    cudaGetSymbolAddress((void**)&carry_p, g_carry);
    cudaGetSymbolAddress((void**)&ebias_p, g_ebias);

    static int attr_done = 0;
    if (!attr_done) {
        cudaFuncSetAttribute(tc_gate, cudaFuncAttributeMaxDynamicSharedMemorySize, GT_SMEM);
        cudaFuncSetAttribute(scan_carry, cudaFuncAttributeMaxDynamicSharedMemorySize,
                             BB * NCH * NN * (int)sizeof(float));
        attr_done = 1;
    }

    // 0) weights -> bf16 hi/lo, effective biases
    prep_kernel<<<64, 256>>>(Wp, Ws, Wo, conv_b, bp, bs, ebias_p);

    // 1) fused conv + gate GEMM (Bt|Ct), and u GEMM
    tc_gate<<<MM / 64, 256, GT_SMEM>>>(x, conv_w, ebias_p, bt_p, ct_p);
    tc_u<<<MM / 64, 128>>>(x, ebias_p, u_p);

    // 2) chunk-parallel scan -> y (bf16 hi/lo)
    scan_partial<<<dim3(NCH / 4, BB), 256>>>(A_log, dt_log, u_p, bt_p, carry_p);
    scan_carry<<<1, 256, BB * NCH * NN * sizeof(float)>>>(A_log, dt_log, carry_p);
    scan_final<<<dim3(NCH / 4, BB), 256>>>(A_log, dt_log, u_p, bt_p, ct_p, carry_p);

    // 3) out = y @ Wo + bo
    tc_out<<<dim3(MM / 64, DD / 128), 256>>>(bo, out);
}

// round 9
// speedup vs baseline: 1.9158x; 1.1798x over previous
#include <cuda_runtime.h>
#include <cuda_bf16.h>
#include <math.h>
#include <stdint.h>

// Problem dims (fixed by the dataset)
#define BB 4
#define LL 4096
#define DD 1024
#define NN 64
#define MM (BB * LL)
#define NCH 128
#define TCH (LL / NCH)    // 32

typedef unsigned int u32;
typedef __nv_bfloat16 bf16;

// ---------------- scratch (device globals: no allocation allowed) ----------------
__device__ bf16 g_WpH[DD * 2 * NN], g_WpL[DD * 2 * NN];   // [1024][128]
__device__ bf16 g_WsH[DD * NN],     g_WsL[DD * NN];       // [1024][64]
__device__ bf16 g_WoH[NN * DD],     g_WoL[NN * DD];       // [64][1024]
__device__ float g_Bt[MM * NN];
__device__ float g_Ct[MM * NN];
__device__ float g_u [MM * NN];
__device__ bf16  g_yH[MM * NN], g_yL[MM * NN];            // [16384][64]
__device__ float g_carry[BB * NCH * NN];
__device__ float g_ebias[3 * NN];

// ---------------- helpers ----------------
#define SW128(o) ((u32)(o) ^ ((((u32)(o)) >> 3) & 0x70))

__device__ __forceinline__ u32 s2u(const void* p) {
    u32 a;
    asm("{ .reg .u64 t; cvta.to.shared.u64 t, %1; cvt.u32.u64 %0, t; }" : "=r"(a) : "l"(p));
    return a;
}
__device__ __forceinline__ float sp(float v) { return v > 20.f ? v : log1pf(expf(v)); }

#define LDSM4(r, a)                                                                    \
    asm volatile("ldmatrix.sync.aligned.m8n8.x4.shared.b16 {%0,%1,%2,%3}, [%4];"      \
                 : "=r"((r)[0]), "=r"((r)[1]), "=r"((r)[2]), "=r"((r)[3]) : "r"(a))
#define LDSM2T(r, a)                                                                   \
    asm volatile("ldmatrix.sync.aligned.m8n8.x2.trans.shared.b16 {%0,%1}, [%2];"      \
                 : "=r"((r)[0]), "=r"((r)[1]) : "r"(a))
#define MMA(d, a, b)                                                                   \
    asm volatile("mma.sync.aligned.m16n8k16.row.col.f32.bf16.bf16.f32 "               \
                 "{%0,%1,%2,%3}, {%4,%5,%6,%7}, {%8,%9}, {%0,%1,%2,%3};"              \
                 : "+f"((d)[0]), "+f"((d)[1]), "+f"((d)[2]), "+f"((d)[3])             \
                 : "r"((a)[0]), "r"((a)[1]), "r"((a)[2]), "r"((a)[3]),                \
                   "r"((b)[0]), "r"((b)[1]))

#define CPA16(sa, gp)                                                                  \
    asm volatile("cp.async.cg.shared.global [%0], [%1], 16;" :: "r"((u32)(sa)), "l"(gp))
#define CPA_COMMIT() asm volatile("cp.async.commit_group;" ::: "memory")
#define CPA_WAIT1()  asm volatile("cp.async.wait_group 1;" ::: "memory")
#define CPA_WAIT0()  asm volatile("cp.async.wait_group 0;" ::: "memory")

__device__ __forceinline__ void split1(float v, bf16& h, bf16& l) {
    h = __float2bfloat16(v);
    l = __float2bfloat16(v - __bfloat162float(h));
}
__device__ __forceinline__ void split_store8(char* hiP, char* loP, float4 v) {
    bf16 h0, l0, h1, l1, h2, l2, h3, l3;
    split1(v.x, h0, l0); split1(v.y, h1, l1);
    split1(v.z, h2, l2); split1(v.w, h3, l3);
    __nv_bfloat162 hp0 = {h0, h1}, hp1 = {h2, h3};
    __nv_bfloat162 lp0 = {l0, l1}, lp1 = {l2, l3};
    *(uint2*)hiP = make_uint2(*(u32*)&hp0, *(u32*)&hp1);
    *(uint2*)loP = make_uint2(*(u32*)&lp0, *(u32*)&lp1);
}
__device__ __forceinline__ float4 f4fma(float4 acc, float4 a, float4 b) {
    acc.x = fmaf(a.x, b.x, acc.x); acc.y = fmaf(a.y, b.y, acc.y);
    acc.z = fmaf(a.z, b.z, acc.z); acc.w = fmaf(a.w, b.w, acc.w);
    return acc;
}

// ---------------- kernel 0: weight bf16 hi/lo split + ebias ----------------------
__global__ void __launch_bounds__(256) prep_kernel(
    const float* __restrict__ Wp, const float* __restrict__ Ws,
    const float* __restrict__ Wo, const float* __restrict__ cb,
    const float* __restrict__ bp, const float* __restrict__ bs,
    float* __restrict__ ebias)
{
    const int gtid = blockIdx.x * 256 + threadIdx.x;
    const int NT = gridDim.x * 256;

    for (int i = gtid; i < DD * 2 * NN; i += NT) split1(Wp[i], g_WpH[i], g_WpL[i]);
    for (int i = gtid; i < DD * NN;     i += NT) split1(Ws[i], g_WsH[i], g_WsL[i]);
    for (int i = gtid; i < NN * DD;     i += NT) split1(Wo[i], g_WoH[i], g_WoL[i]);

    if (gtid < 2 * NN) {
        float s = bp[gtid];
#pragma unroll 8
        for (int d = 0; d < DD; ++d) s = fmaf(cb[d], Wp[(size_t)d * 2 * NN + gtid], s);
        ebias[gtid] = s;
    } else if (gtid < 3 * NN) {
        ebias[gtid] = bs[gtid - 2 * NN];
    }
}

// ---------------- kernel 1: fused conv + gates (N=128) + u (N=64) ----------------
// 384 threads, 12 warps: warps 0-7 gates (2x4, conv-A vs Wp), warps 8-11 u (2x2,
// raw-x-A vs Ws). M-tile 64, BK=64, cp.async double-buffered staging.
// dyn smem layout (all 1024-aligned):
#define FX(b)   (0      + (b) * 17408)   // raw x: 67 rows x 256B
#define FBPH(b) (34816  + (b) * 16384)   // Wp hi: 64x128 bf16, 2 panels SW128
#define FBPL(b) (67584  + (b) * 16384)
#define FBSH(b) (100352 + (b) * 8192)    // Ws hi: 64x64 bf16 SW128
#define FBSL(b) (116736 + (b) * 8192)
#define FACH(b) (133120 + (b) * 8192)    // conv split hi
#define FACL(b) (149504 + (b) * 8192)
#define FAXH(b) (165888 + (b) * 8192)    // x split hi
#define FAXL(b) (182272 + (b) * 8192)
#define FUSED_SMEM 198656

__global__ void __launch_bounds__(384, 1) tc_fused(
    const float* __restrict__ x, const float* __restrict__ cw,
    const float* __restrict__ ebias)
{
    extern __shared__ char dsm[];
    const int tid = threadIdx.x;
    const int lane = tid & 31, w = tid >> 5;
    const int m0 = blockIdx.x * 64;
    const bool seqstart = ((m0 & (LL - 1)) == 0);

    const bool is_gate = (w < 8);
    const int mw = is_gate ? ((w >> 2) * 32) : (((w - 8) >> 1) * 32);
    const int nw = is_gate ? ((w & 3) * 32) : (((w - 8) & 1) * 32);

    float acc[2][4][4];
#pragma unroll
    for (int mt = 0; mt < 2; ++mt)
#pragma unroll
        for (int nt = 0; nt < 4; ++nt)
#pragma unroll
            for (int q = 0; q < 4; ++q) acc[mt][nt][q] = 0.f;

    const int arow = lane & 15, acol = (lane >> 4) * 8;
    const int brow = lane & 15;

    const u32 sbase = s2u(dsm);

    // ---- staging: issue cp.async for tile kt into buffer buf ----
    auto stage = [&](int kt, int buf) {
        // raw x rows (m0-3 .. m0+63) x 64 cols
        for (int i = tid; i < 67 * 16; i += 384) {
            int rr = i >> 4, ch = i & 15;
            u32 dst = sbase + FX(buf) + rr * 256 + ch * 16;
            if (seqstart && rr < 3) {
                *(uint4*)(dsm + FX(buf) + rr * 256 + ch * 16) = make_uint4(0, 0, 0, 0);
            } else {
                CPA16(dst, x + (size_t)(m0 - 3 + rr) * DD + kt * 64 + ch * 4);
            }
        }
        // Wp hi/lo: rows kt*64.., 128 cols (256B rows), 2 SW128 panels
        for (int i = tid; i < 64 * 16; i += 384) {
            int r = i >> 4, ch = i & 15;
            size_t gb = (size_t)(kt * 64 + r) * 256 + ch * 16;
            u32 sw = (u32)(ch >> 3) * 8192 + SW128(r * 128 + (ch & 7) * 16);
            CPA16(sbase + FBPH(buf) + sw, (const char*)g_WpH + gb);
            CPA16(sbase + FBPL(buf) + sw, (const char*)g_WpL + gb);
        }
        // Ws hi/lo: rows kt*64.., 64 cols (128B rows)
        for (int i = tid; i < 64 * 8; i += 384) {
            int r = i >> 3, ch = i & 7;
            size_t gb = (size_t)(kt * 64 + r) * 128 + ch * 16;
            u32 sw = SW128(r * 128 + ch * 16);
            CPA16(sbase + FBSH(buf) + sw, (const char*)g_WsH + gb);
            CPA16(sbase + FBSL(buf) + sw, (const char*)g_WsL + gb);
        }
    };

    stage(0, 0);
    CPA_COMMIT();

    for (int kt = 0; kt < DD / 64; ++kt) {
        const int buf = kt & 1;
        if (kt + 1 < DD / 64) {
            stage(kt + 1, buf ^ 1);
            CPA_COMMIT();
            CPA_WAIT1();
        } else {
            CPA_WAIT0();
        }
        __syncthreads();   // sX/B tiles (buf) visible to all

        // ---- conv + split -> sAc(buf); raw x split -> sAx(buf) ----
        char* sX = dsm + FX(buf);
#pragma unroll
        for (int i = tid; i < 64 * 16; i += 384) {
            int r = i >> 4, ch = i & 15;
            float4 xm3 = *(const float4*)(sX + (r + 0) * 256 + ch * 16);
            float4 xm2 = *(const float4*)(sX + (r + 1) * 256 + ch * 16);
            float4 xm1 = *(const float4*)(sX + (r + 2) * 256 + ch * 16);
            float4 xc  = *(const float4*)(sX + (r + 3) * 256 + ch * 16);
            int dcol = kt * 64 + ch * 4;
            float4 w0 = *(const float4*)(cw + 0 * DD + dcol);
            float4 w1 = *(const float4*)(cw + 1 * DD + dcol);
            float4 w2 = *(const float4*)(cw + 2 * DD + dcol);
            float4 w3 = *(const float4*)(cw + 3 * DD + dcol);
            float4 o = make_float4(0.f, 0.f, 0.f, 0.f);
            o = f4fma(o, w0, xm3); o = f4fma(o, w1, xm2);
            o = f4fma(o, w2, xm1); o = f4fma(o, w3, xc);
            u32 sw = SW128(r * 128 + ch * 8);
            split_store8(dsm + FACH(buf) + sw, dsm + FACL(buf) + sw, o);
            split_store8(dsm + FAXH(buf) + sw, dsm + FAXL(buf) + sw, xc);
        }
        __syncthreads();   // splits (buf) visible

        // ---- MMA ----
        const u32 aH = sbase + (is_gate ? FACH(buf) : FAXH(buf));
        const u32 aL = sbase + (is_gate ? FACL(buf) : FAXL(buf));
        const u32 bH = sbase + (is_gate ? FBPH(buf) : FBSH(buf));
        const u32 bL = sbase + (is_gate ? FBPL(buf) : FBSL(buf));
#pragma unroll
        for (int ks = 0; ks < 4; ++ks) {
            u32 ah[2][4], al[2][4], bh[4][2], bl[4][2];
#pragma unroll
            for (int mt = 0; mt < 2; ++mt) {
                u32 off = SW128((mw + mt * 16 + arow) * 128 + (ks * 16 + acol) * 2);
                LDSM4(ah[mt], aH + off);
                LDSM4(al[mt], aL + off);
            }
#pragma unroll
            for (int nt = 0; nt < 4; ++nt) {
                int col = nw + nt * 8;
                u32 off = (u32)(col >> 6) * 8192 +
                          SW128((ks * 16 + brow) * 128 + (col & 63) * 2);
                LDSM2T(bh[nt], bH + off);
                LDSM2T(bl[nt], bL + off);
            }
#pragma unroll
            for (int mt = 0; mt < 2; ++mt)
#pragma unroll
                for (int nt = 0; nt < 4; ++nt) {
                    MMA(acc[mt][nt], ah[mt], bh[nt]);
                    MMA(acc[mt][nt], ah[mt], bl[nt]);
                    MMA(acc[mt][nt], al[mt], bh[nt]);
                }
        }
        // REQUIRED: next iteration's stage() cp.asyncs overwrite the buffer this
        // iteration's MMA reads (buf(kt+1) stages into buf(kt-1) parity = buf^1,
        // but buf(kt+2) stages into buf — readers must all be done first).
        __syncthreads();
    }

    // ---- epilogue ----
#pragma unroll
    for (int mt = 0; mt < 2; ++mt)
#pragma unroll
        for (int nt = 0; nt < 4; ++nt) {
            int r0 = m0 + mw + mt * 16 + (lane >> 2);
            int col = nw + nt * 8 + 2 * (lane & 3);
            if (is_gate) {
                float b0v = ebias[col], b1v = ebias[col + 1];
                float vx = acc[mt][nt][0] + b0v, vy = acc[mt][nt][1] + b1v;
                float vz = acc[mt][nt][2] + b0v, vw = acc[mt][nt][3] + b1v;
                if (col < 64) {
                    vx = sp(vx); vy = sp(vy); vz = sp(vz); vw = sp(vw);
                    *(float2*)&g_Bt[(size_t)r0 * NN + col] = make_float2(vx, vy);
                    *(float2*)&g_Bt[(size_t)(r0 + 8) * NN + col] = make_float2(vz, vw);
                } else {
                    vx = tanhf(vx); vy = tanhf(vy); vz = tanhf(vz); vw = tanhf(vw);
                    *(float2*)&g_Ct[(size_t)r0 * NN + col - 64] = make_float2(vx, vy);
                    *(float2*)&g_Ct[(size_t)(r0 + 8) * NN + col - 64] = make_float2(vz, vw);
                }
            } else {
                float b0v = ebias[2 * NN + col], b1v = ebias[2 * NN + col + 1];
                *(float2*)&g_u[(size_t)r0 * NN + col] =
                    make_float2(acc[mt][nt][0] + b0v, acc[mt][nt][1] + b1v);
                *(float2*)&g_u[(size_t)(r0 + 8) * NN + col] =
                    make_float2(acc[mt][nt][2] + b0v, acc[mt][nt][3] + b1v);
            }
        }
}

// ---------------- kernel 2: out = y @ Wo + bo (N-tile 128, K=64) -----------------
__global__ void __launch_bounds__(256) tc_out(
    const float* __restrict__ bo, float* __restrict__ out)
{
    __shared__ __align__(1024) char sAh[8192], sAl[8192], sBh[16384], sBl[16384];
    const int tid = threadIdx.x;
    const int lane = tid & 31, w = tid >> 5;
    const int mw = (w >> 2) * 32, nw = (w & 3) * 32;
    const int m0 = blockIdx.x * 64;
    const int n0 = blockIdx.y * 128;

    const u32 aAh = s2u(sAh), aAl = s2u(sAl), aBh = s2u(sBh), aBl = s2u(sBl);

#pragma unroll
    for (int i = tid; i < 64 * 8; i += 256) {
        int r = i >> 3, ch = i & 7;
        size_t gb = (size_t)(m0 + r) * 128 + ch * 16;
        u32 sw = SW128(r * 128 + ch * 16);
        CPA16(aAh + sw, (const char*)g_yH + gb);
        CPA16(aAl + sw, (const char*)g_yL + gb);
    }
#pragma unroll
    for (int i = tid; i < 64 * 16; i += 256) {
        int r = i >> 4, ch = i & 15;
        size_t gb = (size_t)r * 2048 + (size_t)n0 * 2 + ch * 16;
        u32 sw = (u32)(ch >> 3) * 8192 + SW128(r * 128 + (ch & 7) * 16);
        CPA16(aBh + sw, (const char*)g_WoH + gb);
        CPA16(aBl + sw, (const char*)g_WoL + gb);
    }
    CPA_COMMIT();
    CPA_WAIT0();
    __syncthreads();

    float acc[2][4][4];
#pragma unroll
    for (int mt = 0; mt < 2; ++mt)
#pragma unroll
        for (int nt = 0; nt < 4; ++nt)
#pragma unroll
            for (int q = 0; q < 4; ++q) acc[mt][nt][q] = 0.f;

    const int arow = lane & 15, acol = (lane >> 4) * 8;
    const int brow = lane & 15;

#pragma unroll
    for (int ks = 0; ks < 4; ++ks) {
        u32 ah[2][4], al[2][4], bh[4][2], bl[4][2];
#pragma unroll
        for (int mt = 0; mt < 2; ++mt) {
            u32 off = SW128((mw + mt * 16 + arow) * 128 + (ks * 16 + acol) * 2);
            LDSM4(ah[mt], aAh + off);
            LDSM4(al[mt], aAl + off);
        }
#pragma unroll
        for (int nt = 0; nt < 4; ++nt) {
            int col = nw + nt * 8;
            u32 off = (u32)(col >> 6) * 8192 +
                      SW128((ks * 16 + brow) * 128 + (col & 63) * 2);
            LDSM2T(bh[nt], aBh + off);
            LDSM2T(bl[nt], aBl + off);
        }
#pragma unroll
        for (int mt = 0; mt < 2; ++mt)
#pragma unroll
            for (int nt = 0; nt < 4; ++nt) {
                MMA(acc[mt][nt], ah[mt], bh[nt]);
                MMA(acc[mt][nt], ah[mt], bl[nt]);
                MMA(acc[mt][nt], al[mt], bh[nt]);
            }
    }

#pragma unroll
    for (int mt = 0; mt < 2; ++mt)
#pragma unroll
        for (int nt = 0; nt < 4; ++nt) {
            int r0 = m0 + mw + mt * 16 + (lane >> 2);
            int col = n0 + nw + nt * 8 + 2 * (lane & 3);
            float b0v = bo[col], b1v = bo[col + 1];
            *(float2*)&out[(size_t)r0 * DD + col] =
                make_float2(acc[mt][nt][0] + b0v, acc[mt][nt][1] + b1v);
            *(float2*)&out[(size_t)(r0 + 8) * DD + col] =
                make_float2(acc[mt][nt][2] + b0v, acc[mt][nt][3] + b1v);
        }
}

// ---------------- scan kernels (chunk-parallel linear recurrence) ----------------
__global__ void __launch_bounds__(256) scan_partial(
    const float* __restrict__ A_log, const float* __restrict__ dt_log,
    const float* __restrict__ u, const float* __restrict__ Bt,
    float* __restrict__ carry)
{
    const int n = threadIdx.x & 63;
    const int ch = blockIdx.x * 4 + (threadIdx.x >> 6);
    const int b = blockIdx.y;
    const float dt = sp(dt_log[n]);
    const float decay = 1.f - dt * sp(A_log[n]);
    size_t base = ((size_t)b * LL + (size_t)ch * TCH) * NN + n;
    float s = 0.f;
#pragma unroll 8
    for (int t = 0; t < TCH; ++t) {
        float uu = u[base + (size_t)t * NN];
        float bt = Bt[base + (size_t)t * NN];
        s = fmaf(decay, s, (dt * bt) * uu);
    }
    carry[((size_t)b * NCH + ch) * NN + n] = s;
}

// single block, all carries resident in smem (BB*NCH*NN floats = 128 KB)
__global__ void __launch_bounds__(256) scan_carry(
    const float* __restrict__ A_log, const float* __restrict__ dt_log,
    float* __restrict__ carry)
{
    extern __shared__ float sc[];
    const int tid = threadIdx.x;
    const int total = BB * NCH * NN;
    for (int i = tid * 4; i < total; i += 256 * 4)
        *(float4*)&sc[i] = *(const float4*)&carry[i];
    __syncthreads();

    const int b = tid >> 6, n = tid & 63;
    const float dt = sp(dt_log[n]);
    const float decay = 1.f - dt * sp(A_log[n]);
    float dp = decay;
#pragma unroll
    for (int i = 0; i < 5; ++i) dp *= dp;          // decay^32
    float c = 0.f;
#pragma unroll 4
    for (int ch = 0; ch < NCH; ++ch) {
        int idx = (b * NCH + ch) * NN + n;
        float e = sc[idx];
        sc[idx] = c;
        c = fmaf(dp, c, e);
    }
    __syncthreads();
    for (int i = tid * 4; i < total; i += 256 * 4)
        *(float4*)&carry[i] = *(const float4*)&sc[i];
}

__global__ void __launch_bounds__(256) scan_final(
    const float* __restrict__ A_log, const float* __restrict__ dt_log,
    const float* __restrict__ u, const float* __restrict__ Bt,
    const float* __restrict__ Ct, const float* __restrict__ carry)
{
    const int n = threadIdx.x & 63;
    const int ch = blockIdx.x * 4 + (threadIdx.x >> 6);
    const int b = blockIdx.y;
    const float dt = sp(dt_log[n]);
    const float decay = 1.f - dt * sp(A_log[n]);
    size_t base = ((size_t)b * LL + (size_t)ch * TCH) * NN + n;
    float s = carry[((size_t)b * NCH + ch) * NN + n];
#pragma unroll 8
    for (int t = 0; t < TCH; ++t) {
        size_t idx = base + (size_t)t * NN;
        float uu = u[idx];
        float bt = Bt[idx];
        float ct = Ct[idx];
        s = fmaf(decay, s, (dt * bt) * uu);
        float yv = ct * s;
        split1(yv, g_yH[idx], g_yL[idx]);
    }
}

// ---------------- launch ----------------
extern "C" void kernel_launch(void* const* d_in, const int* in_sizes, int n_in,
                              void* d_out, int out_size)
{
    const float* x      = (const float*)d_in[0];
    const float* conv_w = (const float*)d_in[1];
    const float* conv_b = (const float*)d_in[2];
    const float* Wp     = (const float*)d_in[3];
    const float* bp     = (const float*)d_in[4];
    const float* Ws     = (const float*)d_in[5];
    const float* bs     = (const float*)d_in[6];
    const float* A_log  = (const float*)d_in[7];
    const float* dt_log = (const float*)d_in[8];
    const float* Wo     = (const float*)d_in[9];
    const float* bo     = (const float*)d_in[10];
    float* out = (float*)d_out;

    float *bt_p, *ct_p, *u_p, *carry_p, *ebias_p;
    cudaGetSymbolAddress((void**)&bt_p,    g_Bt);
    cudaGetSymbolAddress((void**)&ct_p,    g_Ct);
    cudaGetSymbolAddress((void**)&u_p,     g_u);
    cudaGetSymbolAddress((void**)&carry_p, g_carry);
    cudaGetSymbolAddress((void**)&ebias_p, g_ebias);

    static int attr_done = 0;
    if (!attr_done) {
        cudaFuncSetAttribute(tc_fused, cudaFuncAttributeMaxDynamicSharedMemorySize, FUSED_SMEM);
        cudaFuncSetAttribute(scan_carry, cudaFuncAttributeMaxDynamicSharedMemorySize,
                             BB * NCH * NN * (int)sizeof(float));
        attr_done = 1;
    }

    // 0) weights -> bf16 hi/lo, effective biases
    prep_kernel<<<64, 256>>>(Wp, Ws, Wo, conv_b, bp, bs, ebias_p);

    // 1) fused conv + gate GEMM (Bt|Ct) + u GEMM
    tc_fused<<<MM / 64, 384, FUSED_SMEM>>>(x, conv_w, ebias_p);

    // 2) chunk-parallel scan -> y (bf16 hi/lo)
    scan_partial<<<dim3(NCH / 4, BB), 256>>>(A_log, dt_log, u_p, bt_p, carry_p);
    scan_carry<<<1, 256, BB * NCH * NN * sizeof(float)>>>(A_log, dt_log, carry_p);
    scan_final<<<dim3(NCH / 4, BB), 256>>>(A_log, dt_log, u_p, bt_p, ct_p, carry_p);

    // 3) out = y @ Wo + bo
    tc_out<<<dim3(MM / 64, DD / 128), 256>>>(bo, out);
}

// round 10
// speedup vs baseline: 1.9185x; 1.0014x over previous
#include <cuda_runtime.h>
#include <cuda_bf16.h>
#include <math.h>
#include <stdint.h>

// Problem dims (fixed by the dataset)
#define BB 4
#define LL 4096
#define DD 1024
#define NN 64
#define MM (BB * LL)
#define NCH 128
#define TCH (LL / NCH)    // 32

typedef unsigned int u32;
typedef __nv_bfloat16 bf16;

// ---------------- scratch (device globals: no allocation allowed) ----------------
__device__ bf16 g_WpH[DD * 2 * NN], g_WpL[DD * 2 * NN];   // [1024][128]
__device__ bf16 g_WsH[DD * NN],     g_WsL[DD * NN];       // [1024][64]
__device__ bf16 g_WoH[NN * DD],     g_WoL[NN * DD];       // [64][1024]
__device__ float g_P [MM * NN];                            // dt * Bt * u
__device__ float g_Ct[MM * NN];
__device__ bf16  g_yH[MM * NN], g_yL[MM * NN];            // [16384][64]
__device__ float g_carryT[BB * NN * NCH];                 // transposed carries
__device__ float g_ebias[3 * NN];
__device__ float g_sd[3 * NN];                            // dt | decay | decay^TCH

// ---------------- helpers ----------------
#define SW128(o) ((u32)(o) ^ ((((u32)(o)) >> 3) & 0x70))

__device__ __forceinline__ u32 s2u(const void* p) {
    u32 a;
    asm("{ .reg .u64 t; cvta.to.shared.u64 t, %1; cvt.u32.u64 %0, t; }" : "=r"(a) : "l"(p));
    return a;
}
__device__ __forceinline__ float sp(float v) { return v > 20.f ? v : log1pf(expf(v)); }

#define LDSM4(r, a)                                                                    \
    asm volatile("ldmatrix.sync.aligned.m8n8.x4.shared.b16 {%0,%1,%2,%3}, [%4];"      \
                 : "=r"((r)[0]), "=r"((r)[1]), "=r"((r)[2]), "=r"((r)[3]) : "r"(a))
#define LDSM2T(r, a)                                                                   \
    asm volatile("ldmatrix.sync.aligned.m8n8.x2.trans.shared.b16 {%0,%1}, [%2];"      \
                 : "=r"((r)[0]), "=r"((r)[1]) : "r"(a))
#define MMA(d, a, b)                                                                   \
    asm volatile("mma.sync.aligned.m16n8k16.row.col.f32.bf16.bf16.f32 "               \
                 "{%0,%1,%2,%3}, {%4,%5,%6,%7}, {%8,%9}, {%0,%1,%2,%3};"              \
                 : "+f"((d)[0]), "+f"((d)[1]), "+f"((d)[2]), "+f"((d)[3])             \
                 : "r"((a)[0]), "r"((a)[1]), "r"((a)[2]), "r"((a)[3]),                \
                   "r"((b)[0]), "r"((b)[1]))

#define CPA16(sa, gp)                                                                  \
    asm volatile("cp.async.cg.shared.global [%0], [%1], 16;" :: "r"((u32)(sa)), "l"(gp))
#define CPA_COMMIT() asm volatile("cp.async.commit_group;" ::: "memory")
#define CPA_WAIT1()  asm volatile("cp.async.wait_group 1;" ::: "memory")
#define CPA_WAIT0()  asm volatile("cp.async.wait_group 0;" ::: "memory")

__device__ __forceinline__ void split1(float v, bf16& h, bf16& l) {
    h = __float2bfloat16(v);
    l = __float2bfloat16(v - __bfloat162float(h));
}
__device__ __forceinline__ void split_store8(char* hiP, char* loP, float4 v) {
    bf16 h0, l0, h1, l1, h2, l2, h3, l3;
    split1(v.x, h0, l0); split1(v.y, h1, l1);
    split1(v.z, h2, l2); split1(v.w, h3, l3);
    __nv_bfloat162 hp0 = {h0, h1}, hp1 = {h2, h3};
    __nv_bfloat162 lp0 = {l0, l1}, lp1 = {l2, l3};
    *(uint2*)hiP = make_uint2(*(u32*)&hp0, *(u32*)&hp1);
    *(uint2*)loP = make_uint2(*(u32*)&lp0, *(u32*)&lp1);
}
__device__ __forceinline__ float4 f4fma(float4 acc, float4 a, float4 b) {
    acc.x = fmaf(a.x, b.x, acc.x); acc.y = fmaf(a.y, b.y, acc.y);
    acc.z = fmaf(a.z, b.z, acc.z); acc.w = fmaf(a.w, b.w, acc.w);
    return acc;
}

// ---------------- kernel 0: weight bf16 hi/lo split + ebias + scan consts --------
__global__ void __launch_bounds__(256) prep_kernel(
    const float* __restrict__ Wp, const float* __restrict__ Ws,
    const float* __restrict__ Wo, const float* __restrict__ cb,
    const float* __restrict__ bp, const float* __restrict__ bs,
    const float* __restrict__ A_log, const float* __restrict__ dt_log,
    float* __restrict__ ebias, float* __restrict__ sd)
{
    const int gtid = blockIdx.x * 256 + threadIdx.x;
    const int NT = gridDim.x * 256;

    for (int i = gtid; i < DD * 2 * NN; i += NT) split1(Wp[i], g_WpH[i], g_WpL[i]);
    for (int i = gtid; i < DD * NN;     i += NT) split1(Ws[i], g_WsH[i], g_WsL[i]);
    for (int i = gtid; i < NN * DD;     i += NT) split1(Wo[i], g_WoH[i], g_WoL[i]);

    if (gtid < 2 * NN) {
        float s = bp[gtid];
#pragma unroll 8
        for (int d = 0; d < DD; ++d) s = fmaf(cb[d], Wp[(size_t)d * 2 * NN + gtid], s);
        ebias[gtid] = s;
    } else if (gtid < 3 * NN) {
        ebias[gtid] = bs[gtid - 2 * NN];
    } else if (gtid < 3 * NN + NN) {
        int n = gtid - 3 * NN;
        float dt = sp(dt_log[n]);
        float decay = 1.f - dt * sp(A_log[n]);
        float dp = decay;
#pragma unroll
        for (int i = 0; i < 5; ++i) dp *= dp;      // decay^32
        sd[n] = dt;
        sd[NN + n] = decay;
        sd[2 * NN + n] = dp;
    }
}

// ---------------- kernel 1: fused conv + gates + u, emits P = dt*Bt*u and Ct -----
// 384 threads, 12 warps: warps 0-7 gates (2x4, conv-A vs Wp), warps 8-11 u (2x2,
// raw-x-A vs Ws). M-tile 64, BK=64, cp.async double-buffered staging.
#define FX(b)   (0      + (b) * 17408)   // raw x: 67 rows x 256B
#define FBPH(b) (34816  + (b) * 16384)   // Wp hi: 64x128 bf16, 2 panels SW128
#define FBPL(b) (67584  + (b) * 16384)
#define FBSH(b) (100352 + (b) * 8192)    // Ws hi: 64x64 bf16 SW128
#define FBSL(b) (116736 + (b) * 8192)
#define FACH(b) (133120 + (b) * 8192)    // conv split hi
#define FACL(b) (149504 + (b) * 8192)
#define FAXH(b) (165888 + (b) * 8192)    // x split hi
#define FAXL(b) (182272 + (b) * 8192)
#define FUSED_SMEM 198656
#define USTRIDE 66                       // u exchange row stride (floats)

__global__ void __launch_bounds__(384, 1) tc_fused(
    const float* __restrict__ x, const float* __restrict__ cw,
    const float* __restrict__ ebias, const float* __restrict__ sd)
{
    extern __shared__ char dsm[];
    const int tid = threadIdx.x;
    const int lane = tid & 31, w = tid >> 5;
    const int m0 = blockIdx.x * 64;
    const bool seqstart = ((m0 & (LL - 1)) == 0);

    const bool is_gate = (w < 8);
    const int mw = is_gate ? ((w >> 2) * 32) : (((w - 8) >> 1) * 32);
    const int nw = is_gate ? ((w & 3) * 32) : (((w - 8) & 1) * 32);

    float acc[2][4][4];
#pragma unroll
    for (int mt = 0; mt < 2; ++mt)
#pragma unroll
        for (int nt = 0; nt < 4; ++nt)
#pragma unroll
            for (int q = 0; q < 4; ++q) acc[mt][nt][q] = 0.f;

    const int arow = lane & 15, acol = (lane >> 4) * 8;
    const int brow = lane & 15;

    const u32 sbase = s2u(dsm);

    auto stage = [&](int kt, int buf) {
        for (int i = tid; i < 67 * 16; i += 384) {
            int rr = i >> 4, ch = i & 15;
            u32 dst = sbase + FX(buf) + rr * 256 + ch * 16;
            if (seqstart && rr < 3) {
                *(uint4*)(dsm + FX(buf) + rr * 256 + ch * 16) = make_uint4(0, 0, 0, 0);
            } else {
                CPA16(dst, x + (size_t)(m0 - 3 + rr) * DD + kt * 64 + ch * 4);
            }
        }
        for (int i = tid; i < 64 * 16; i += 384) {
            int r = i >> 4, ch = i & 15;
            size_t gb = (size_t)(kt * 64 + r) * 256 + ch * 16;
            u32 sw = (u32)(ch >> 3) * 8192 + SW128(r * 128 + (ch & 7) * 16);
            CPA16(sbase + FBPH(buf) + sw, (const char*)g_WpH + gb);
            CPA16(sbase + FBPL(buf) + sw, (const char*)g_WpL + gb);
        }
        for (int i = tid; i < 64 * 8; i += 384) {
            int r = i >> 3, ch = i & 7;
            size_t gb = (size_t)(kt * 64 + r) * 128 + ch * 16;
            u32 sw = SW128(r * 128 + ch * 16);
            CPA16(sbase + FBSH(buf) + sw, (const char*)g_WsH + gb);
            CPA16(sbase + FBSL(buf) + sw, (const char*)g_WsL + gb);
        }
    };

    stage(0, 0);
    CPA_COMMIT();

    for (int kt = 0; kt < DD / 64; ++kt) {
        const int buf = kt & 1;
        if (kt + 1 < DD / 64) {
            stage(kt + 1, buf ^ 1);
            CPA_COMMIT();
            CPA_WAIT1();
        } else {
            CPA_WAIT0();
        }
        __syncthreads();

        // ---- conv + split -> sAc(buf); raw x split -> sAx(buf) ----
        char* sX = dsm + FX(buf);
#pragma unroll
        for (int i = tid; i < 64 * 16; i += 384) {
            int r = i >> 4, ch = i & 15;
            float4 xm3 = *(const float4*)(sX + (r + 0) * 256 + ch * 16);
            float4 xm2 = *(const float4*)(sX + (r + 1) * 256 + ch * 16);
            float4 xm1 = *(const float4*)(sX + (r + 2) * 256 + ch * 16);
            float4 xc  = *(const float4*)(sX + (r + 3) * 256 + ch * 16);
            int dcol = kt * 64 + ch * 4;
            float4 w0 = *(const float4*)(cw + 0 * DD + dcol);
            float4 w1 = *(const float4*)(cw + 1 * DD + dcol);
            float4 w2 = *(const float4*)(cw + 2 * DD + dcol);
            float4 w3 = *(const float4*)(cw + 3 * DD + dcol);
            float4 o = make_float4(0.f, 0.f, 0.f, 0.f);
            o = f4fma(o, w0, xm3); o = f4fma(o, w1, xm2);
            o = f4fma(o, w2, xm1); o = f4fma(o, w3, xc);
            u32 sw = SW128(r * 128 + ch * 8);
            split_store8(dsm + FACH(buf) + sw, dsm + FACL(buf) + sw, o);
            split_store8(dsm + FAXH(buf) + sw, dsm + FAXL(buf) + sw, xc);
        }
        __syncthreads();

        // ---- MMA ----
        const u32 aH = sbase + (is_gate ? FACH(buf) : FAXH(buf));
        const u32 aL = sbase + (is_gate ? FACL(buf) : FAXL(buf));
        const u32 bH = sbase + (is_gate ? FBPH(buf) : FBSH(buf));
        const u32 bL = sbase + (is_gate ? FBPL(buf) : FBSL(buf));
#pragma unroll
        for (int ks = 0; ks < 4; ++ks) {
            u32 ah[2][4], al[2][4], bh[4][2], bl[4][2];
#pragma unroll
            for (int mt = 0; mt < 2; ++mt) {
                u32 off = SW128((mw + mt * 16 + arow) * 128 + (ks * 16 + acol) * 2);
                LDSM4(ah[mt], aH + off);
                LDSM4(al[mt], aL + off);
            }
#pragma unroll
            for (int nt = 0; nt < 4; ++nt) {
                int col = nw + nt * 8;
                u32 off = (u32)(col >> 6) * 8192 +
                          SW128((ks * 16 + brow) * 128 + (col & 63) * 2);
                LDSM2T(bh[nt], bH + off);
                LDSM2T(bl[nt], bL + off);
            }
#pragma unroll
            for (int mt = 0; mt < 2; ++mt)
#pragma unroll
                for (int nt = 0; nt < 4; ++nt) {
                    MMA(acc[mt][nt], ah[mt], bh[nt]);
                    MMA(acc[mt][nt], ah[mt], bl[nt]);
                    MMA(acc[mt][nt], al[mt], bh[nt]);
                }
        }
        // REQUIRED: next iteration's stage() overwrites buffers read above.
        __syncthreads();
    }

    // ---- epilogue: u warps -> smem exchange; gate warps -> P and Ct ----
    float* sU = (float*)dsm;   // 64 x USTRIDE floats (reuses FX region, post-barrier)
    if (!is_gate) {
#pragma unroll
        for (int mt = 0; mt < 2; ++mt)
#pragma unroll
            for (int nt = 0; nt < 4; ++nt) {
                int r = mw + mt * 16 + (lane >> 2);
                int col = nw + nt * 8 + 2 * (lane & 3);
                float b0v = ebias[2 * NN + col], b1v = ebias[2 * NN + col + 1];
                sU[r * USTRIDE + col]           = acc[mt][nt][0] + b0v;
                sU[r * USTRIDE + col + 1]       = acc[mt][nt][1] + b1v;
                sU[(r + 8) * USTRIDE + col]     = acc[mt][nt][2] + b0v;
                sU[(r + 8) * USTRIDE + col + 1] = acc[mt][nt][3] + b1v;
            }
    }
    __syncthreads();
    if (is_gate) {
#pragma unroll
        for (int mt = 0; mt < 2; ++mt)
#pragma unroll
            for (int nt = 0; nt < 4; ++nt) {
                int r = mw + mt * 16 + (lane >> 2);
                int col = nw + nt * 8 + 2 * (lane & 3);
                float b0v = ebias[col], b1v = ebias[col + 1];
                float vx = acc[mt][nt][0] + b0v, vy = acc[mt][nt][1] + b1v;
                float vz = acc[mt][nt][2] + b0v, vw = acc[mt][nt][3] + b1v;
                if (col < 64) {
                    float dt0 = sd[col], dt1 = sd[col + 1];
                    float p0 = dt0 * sp(vx) * sU[r * USTRIDE + col];
                    float p1 = dt1 * sp(vy) * sU[r * USTRIDE + col + 1];
                    float p2 = dt0 * sp(vz) * sU[(r + 8) * USTRIDE + col];
                    float p3 = dt1 * sp(vw) * sU[(r + 8) * USTRIDE + col + 1];
                    *(float2*)&g_P[(size_t)(m0 + r) * NN + col] = make_float2(p0, p1);
                    *(float2*)&g_P[(size_t)(m0 + r + 8) * NN + col] = make_float2(p2, p3);
                } else {
                    vx = tanhf(vx); vy = tanhf(vy); vz = tanhf(vz); vw = tanhf(vw);
                    *(float2*)&g_Ct[(size_t)(m0 + r) * NN + col - 64] = make_float2(vx, vy);
                    *(float2*)&g_Ct[(size_t)(m0 + r + 8) * NN + col - 64] = make_float2(vz, vw);
                }
            }
    }
}

// ---------------- kernel 2: out = y @ Wo + bo (N-tile 128, K=64) -----------------
__global__ void __launch_bounds__(256) tc_out(
    const float* __restrict__ bo, float* __restrict__ out)
{
    __shared__ __align__(1024) char sAh[8192], sAl[8192], sBh[16384], sBl[16384];
    const int tid = threadIdx.x;
    const int lane = tid & 31, w = tid >> 5;
    const int mw = (w >> 2) * 32, nw = (w & 3) * 32;
    const int m0 = blockIdx.x * 64;
    const int n0 = blockIdx.y * 128;

    const u32 aAh = s2u(sAh), aAl = s2u(sAl), aBh = s2u(sBh), aBl = s2u(sBl);

#pragma unroll
    for (int i = tid; i < 64 * 8; i += 256) {
        int r = i >> 3, ch = i & 7;
        size_t gb = (size_t)(m0 + r) * 128 + ch * 16;
        u32 sw = SW128(r * 128 + ch * 16);
        CPA16(aAh + sw, (const char*)g_yH + gb);
        CPA16(aAl + sw, (const char*)g_yL + gb);
    }
#pragma unroll
    for (int i = tid; i < 64 * 16; i += 256) {
        int r = i >> 4, ch = i & 15;
        size_t gb = (size_t)r * 2048 + (size_t)n0 * 2 + ch * 16;
        u32 sw = (u32)(ch >> 3) * 8192 + SW128(r * 128 + (ch & 7) * 16);
        CPA16(aBh + sw, (const char*)g_WoH + gb);
        CPA16(aBl + sw, (const char*)g_WoL + gb);
    }
    CPA_COMMIT();
    CPA_WAIT0();
    __syncthreads();

    float acc[2][4][4];
#pragma unroll
    for (int mt = 0; mt < 2; ++mt)
#pragma unroll
        for (int nt = 0; nt < 4; ++nt)
#pragma unroll
            for (int q = 0; q < 4; ++q) acc[mt][nt][q] = 0.f;

    const int arow = lane & 15, acol = (lane >> 4) * 8;
    const int brow = lane & 15;

#pragma unroll
    for (int ks = 0; ks < 4; ++ks) {
        u32 ah[2][4], al[2][4], bh[4][2], bl[4][2];
#pragma unroll
        for (int mt = 0; mt < 2; ++mt) {
            u32 off = SW128((mw + mt * 16 + arow) * 128 + (ks * 16 + acol) * 2);
            LDSM4(ah[mt], aAh + off);
            LDSM4(al[mt], aAl + off);
        }
#pragma unroll
        for (int nt = 0; nt < 4; ++nt) {
            int col = nw + nt * 8;
            u32 off = (u32)(col >> 6) * 8192 +
                      SW128((ks * 16 + brow) * 128 + (col & 63) * 2);
            LDSM2T(bh[nt], aBh + off);
            LDSM2T(bl[nt], aBl + off);
        }
#pragma unroll
        for (int mt = 0; mt < 2; ++mt)
#pragma unroll
            for (int nt = 0; nt < 4; ++nt) {
                MMA(acc[mt][nt], ah[mt], bh[nt]);
                MMA(acc[mt][nt], ah[mt], bl[nt]);
                MMA(acc[mt][nt], al[mt], bh[nt]);
            }
    }

#pragma unroll
    for (int mt = 0; mt < 2; ++mt)
#pragma unroll
        for (int nt = 0; nt < 4; ++nt) {
            int r0 = m0 + mw + mt * 16 + (lane >> 2);
            int col = n0 + nw + nt * 8 + 2 * (lane & 3);
            float b0v = bo[col], b1v = bo[col + 1];
            *(float2*)&out[(size_t)r0 * DD + col] =
                make_float2(acc[mt][nt][0] + b0v, acc[mt][nt][1] + b1v);
            *(float2*)&out[(size_t)(r0 + 8) * DD + col] =
                make_float2(acc[mt][nt][2] + b0v, acc[mt][nt][3] + b1v);
        }
}

// ---------------- scan kernels (chunk-parallel linear recurrence) ----------------
__global__ void __launch_bounds__(256) scan_partial(
    const float* __restrict__ P, const float* __restrict__ sd,
    float* __restrict__ carryT)
{
    const int n = threadIdx.x & 63;
    const int ch = blockIdx.x * 4 + (threadIdx.x >> 6);
    const int b = blockIdx.y;
    const float decay = sd[NN + n];
    const float* p = P + ((size_t)b * LL + (size_t)ch * TCH) * NN + n;
    float s = 0.f;
#pragma unroll
    for (int t = 0; t < TCH; ++t) s = fmaf(decay, s, p[(size_t)t * NN]);
    carryT[((size_t)b * NN + n) * NCH + ch] = s;
}

// 256 threads, one per (b,n): contiguous 128-float row, register chain
__global__ void __launch_bounds__(256) scan_carry(
    const float* __restrict__ sd, float* __restrict__ carryT)
{
    const int tid = threadIdx.x;
    const int b = tid >> 6, n = tid & 63;
    const float dp = sd[2 * NN + n];
    float4* p = (float4*)(carryT + ((size_t)b * NN + n) * NCH);
    float4 v[NCH / 4];
#pragma unroll
    for (int i = 0; i < NCH / 4; ++i) v[i] = p[i];
    float c = 0.f;
#pragma unroll
    for (int i = 0; i < NCH / 4; ++i) {
        float e;
        e = v[i].x; v[i].x = c; c = fmaf(dp, c, e);
        e = v[i].y; v[i].y = c; c = fmaf(dp, c, e);
        e = v[i].z; v[i].z = c; c = fmaf(dp, c, e);
        e = v[i].w; v[i].w = c; c = fmaf(dp, c, e);
    }
#pragma unroll
    for (int i = 0; i < NCH / 4; ++i) p[i] = v[i];
}

__global__ void __launch_bounds__(256) scan_final(
    const float* __restrict__ P, const float* __restrict__ Ct,
    const float* __restrict__ sd, const float* __restrict__ carryT)
{
    const int n = threadIdx.x & 63;
    const int ch = blockIdx.x * 4 + (threadIdx.x >> 6);
    const int b = blockIdx.y;
    const float decay = sd[NN + n];
    size_t base = ((size_t)b * LL + (size_t)ch * TCH) * NN + n;
    float s = carryT[((size_t)b * NN + n) * NCH + ch];
#pragma unroll
    for (int t = 0; t < TCH; ++t) {
        size_t idx = base + (size_t)t * NN;
        s = fmaf(decay, s, P[idx]);
        float yv = Ct[idx] * s;
        split1(yv, g_yH[idx], g_yL[idx]);
    }
}

// ---------------- launch ----------------
extern "C" void kernel_launch(void* const* d_in, const int* in_sizes, int n_in,
                              void* d_out, int out_size)
{
    const float* x      = (const float*)d_in[0];
    const float* conv_w = (const float*)d_in[1];
    const float* conv_b = (const float*)d_in[2];
    const float* Wp     = (const float*)d_in[3];
    const float* bp     = (const float*)d_in[4];
    const float* Ws     = (const float*)d_in[5];
    const float* bs     = (const float*)d_in[6];
    const float* A_log  = (const float*)d_in[7];
    const float* dt_log = (const float*)d_in[8];
    const float* Wo     = (const float*)d_in[9];
    const float* bo     = (const float*)d_in[10];
    float* out = (float*)d_out;

    float *p_p, *ct_p, *carry_p, *ebias_p, *sd_p;
    cudaGetSymbolAddress((void**)&p_p,     g_P);
    cudaGetSymbolAddress((void**)&ct_p,    g_Ct);
    cudaGetSymbolAddress((void**)&carry_p, g_carryT);
    cudaGetSymbolAddress((void**)&ebias_p, g_ebias);
    cudaGetSymbolAddress((void**)&sd_p,    g_sd);

    static int attr_done = 0;
    if (!attr_done) {
        cudaFuncSetAttribute(tc_fused, cudaFuncAttributeMaxDynamicSharedMemorySize, FUSED_SMEM);
        attr_done = 1;
    }

    // 0) weights -> bf16 hi/lo, effective biases, scan constants
    prep_kernel<<<64, 256>>>(Wp, Ws, Wo, conv_b, bp, bs, A_log, dt_log, ebias_p, sd_p);

    // 1) fused conv + gate GEMM + u GEMM -> P (= dt*Bt*u) and Ct
    tc_fused<<<MM / 64, 384, FUSED_SMEM>>>(x, conv_w, ebias_p, sd_p);

    // 2) chunk-parallel scan -> y (bf16 hi/lo)
    scan_partial<<<dim3(NCH / 4, BB), 256>>>(p_p, sd_p, carry_p);
    scan_carry<<<1, 256>>>(sd_p, carry_p);
    scan_final<<<dim3(NCH / 4, BB), 256>>>(p_p, ct_p, sd_p, carry_p);

    // 3) out = y @ Wo + bo
    tc_out<<<dim3(MM / 64, DD / 128), 256>>>(bo, out);
}